// round 2
// baseline (speedup 1.0000x reference)
#include <cuda_runtime.h>
#include <math.h>

// ---------------------------------------------------------------------------
// PET forward model, restructured:
//  - 128x128 inputs live centered in a 300x300 canvas (all pads are zeros;
//    reflect-pad in the blurs is equivalent to zero-extension since the pad
//    margin (42) exceeds the largest blur radius (8)).
//  - Blurred support is canvas [78,221]^2 -> keep only a 148x148 tile
//    (canvas rows/cols 76..223), two channels (emission, 0.01*attenuation)
//    interleaved as float2.
//  - Radon: px(i,j) = 149.5 + c*(j-149.5) + s*(i-149.5) (unit step in i).
//    Each (angle, detector) walks a line clipped to the support box,
//    bilinear-sampling BOTH channels from the tile staged in shared memory.
//  - Then attenuation correction exp(-2*A), per-angle 5-tap detector blur
//    with reflect, times per-batch scale.
// ---------------------------------------------------------------------------

#define NB 16
#define NA 300
#define ND 300
#define TS 148        // support tile size (canvas 76..223)
#define TSTRIDE 160   // padded row stride (float2 units), room for XOR-16 swizzle
#define G_ANG 4       // angles per radon block

__device__ float2 g_tile[NB][TS][TSTRIDE];   // blurred 2-channel tile (zeros in pads)
__device__ float2 g_tmpH[NB][128][TS];       // horizontally blurred temp
__device__ float  g_sino[NB][NA][ND];        // pre-detector-blur sinogram
__device__ float  g_K4[9];                   // emission blur taps (sigma = 1/sqrt(ln2))
__device__ float  g_K8[17];                  // attenuation blur taps (sigma = 2/sqrt(ln2))
__device__ float2 g_cs[NA];                  // cos/sin per angle
__device__ float  g_ks[NA][5];               // per-angle detector blur taps

// ---------------------------------------------------------------------------
__global__ void init_kernel() {
    int t = threadIdx.x;
    if (t == 0) {
        double sig_i = 1.0 / sqrt(log(2.0));   // FWHM/(4 sqrt(ln2)), FWHM=4mm
        double w4[9], s4 = 0.0;
        for (int d = -4; d <= 4; ++d) { double w = exp(-0.5*(d/sig_i)*(d/sig_i)); w4[d+4] = w; s4 += w; }
        for (int i = 0; i < 9; ++i) g_K4[i] = (float)(w4[i] / s4);
        double sig_a = 2.0 / sqrt(log(2.0));   // FWHM/(2 sqrt(ln2))
        double w8[17], s8 = 0.0;
        for (int d = -8; d <= 8; ++d) { double w = exp(-0.5*(d/sig_a)*(d/sig_a)); w8[d+8] = w; s8 += w; }
        for (int i = 0; i < 17; ++i) g_K8[i] = (float)(w8[i] / s8);
    }
    if (t < NA) {
        double th  = t * (180.0 / 299.0);
        double rad = th * (3.14159265358979323846 / 180.0);
        double c = cos(rad), s = sin(rad);
        g_cs[t] = make_float2((float)c, (float)s);
        double bw  = fabs(2.0 * c) + fabs(2.0 * s);
        double sig = (1.0 / sqrt(log(2.0))) / bw;
        double w[5], sm = 0.0;
        for (int d = -2; d <= 2; ++d) { double ww = exp(-0.5*(d/sig)*(d/sig)); w[d+2] = ww; sm += ww; }
        for (int i = 0; i < 5; ++i) g_ks[t][i] = (float)(w[i] / sm);
    }
}

// ---------------------------------------------------------------------------
// Horizontal blur: input 128x128 images -> tmpH[b][y][c], c = tile col
// (canvas col 76+c -> input col c-10).
__global__ void blur_h(const float* __restrict__ img, const float* __restrict__ att) {
    int idx = blockIdx.x * blockDim.x + threadIdx.x;
    if (idx >= NB * 128 * TS) return;
    int c = idx % TS;
    int y = (idx / TS) % 128;
    int b = idx / (TS * 128);
    const float* ib = img + (b * 128 + y) * 128;
    const float* ab = att + (b * 128 + y) * 128;
    float a0 = 0.f, a1 = 0.f;
    int xc = c - 10;
#pragma unroll
    for (int d = -8; d <= 8; ++d) {
        int xi = xc + d;
        if (xi >= 0 && xi < 128) {
            a1 += g_K8[d + 8] * ab[xi];
            if (d >= -4 && d <= 4) a0 += g_K4[d + 4] * ib[xi];
        }
    }
    g_tmpH[b][y][c] = make_float2(a0, a1);
}

// Vertical blur -> g_tile, applying ATT_SCALE=0.01 to channel 1.
__global__ void blur_v() {
    int idx = blockIdx.x * blockDim.x + threadIdx.x;
    if (idx >= NB * TS * TS) return;
    int c = idx % TS;
    int r = (idx / TS) % TS;
    int b = idx / (TS * TS);
    float a0 = 0.f, a1 = 0.f;
    int yc = r - 10;
#pragma unroll
    for (int d = -8; d <= 8; ++d) {
        int yi = yc + d;
        if (yi >= 0 && yi < 128) {
            float2 t = g_tmpH[b][yi][c];
            a1 += g_K8[d + 8] * t.y;
            if (d >= -4 && d <= 4) a0 += g_K4[d + 4] * t.x;
        }
    }
    g_tile[b][r][c] = make_float2(a0, a1 * 0.01f);
}

// ---------------------------------------------------------------------------
// Radon: block = (angle group, batch). Tile staged in smem with XOR-16 swizzle
// (x stored at column x ^ (y & 15)) to break bank degeneracy for rotated walks.
__global__ __launch_bounds__(640, 1) void radon_kernel() {
    extern __shared__ float2 sm[];
    int b    = blockIdx.y;
    int ang0 = blockIdx.x * G_ANG;

    const float2* src = &g_tile[b][0][0];
    for (int i = threadIdx.x; i < TS * TSTRIDE; i += blockDim.x) {
        int y = i / TSTRIDE;
        int x = i - y * TSTRIDE;
        sm[y * TSTRIDE + (x ^ (y & 15))] = src[i];
    }
    __syncthreads();

    for (int it = threadIdx.x; it < G_ANG * ND; it += blockDim.x) {
        int al  = it / ND;
        int j   = it - al * ND;
        int ang = ang0 + al;
        float2 cs = g_cs[ang];
        float c = cs.x, s = cs.y;
        float u  = (float)j - 149.5f;
        // local coords (tile origin at canvas 76): lx = bx + s*i, ly = by + c*i
        float bx = 73.5f + c * u - 149.5f * s;
        float by = 73.5f - s * u - 149.5f * c;

        const float LO = 0.999f, HI = 146.001f;   // window where taps can be nonzero
        float t0 = 0.f, t1 = 299.f;
        bool empty = false;
        if (fabsf(s) > 1e-6f) {
            float ra = (LO - bx) / s, rb = (HI - bx) / s;
            t0 = fmaxf(t0, fminf(ra, rb));
            t1 = fminf(t1, fmaxf(ra, rb));
        } else if (bx <= LO || bx >= HI) empty = true;
        if (fabsf(c) > 1e-6f) {
            float ra = (LO - by) / c, rb = (HI - by) / c;
            t0 = fmaxf(t0, fminf(ra, rb));
            t1 = fminf(t1, fmaxf(ra, rb));
        } else if (by <= LO || by >= HI) empty = true;

        float S = 0.f, A = 0.f;
        if (!empty && t0 <= t1) {
            int i0 = (int)ceilf(t0); if (i0 < 0) i0 = 0;
            int i1 = (int)floorf(t1); if (i1 > 299) i1 = 299;
            for (int i = i0; i <= i1; ++i) {
                float lx = fmaf(s, (float)i, bx);
                float ly = fmaf(c, (float)i, by);
                float fx = floorf(lx), fy = floorf(ly);
                int x0 = (int)fx, y0 = (int)fy;
                float wx = lx - fx, wy = ly - fy;
                int m0 = y0 & 15, m1 = (y0 + 1) & 15;
                int r0 = y0 * TSTRIDE, r1 = r0 + TSTRIDE;
                float2 v00 = sm[r0 + ( x0      ^ m0)];
                float2 v01 = sm[r0 + ((x0 + 1) ^ m0)];
                float2 v10 = sm[r1 + ( x0      ^ m1)];
                float2 v11 = sm[r1 + ((x0 + 1) ^ m1)];
                float ta = fmaf(wx, v01.x - v00.x, v00.x);
                float ba = fmaf(wx, v11.x - v10.x, v10.x);
                S += fmaf(wy, ba - ta, ta);
                float tb = fmaf(wx, v01.y - v00.y, v00.y);
                float bb = fmaf(wx, v11.y - v10.y, v10.y);
                A += fmaf(wy, bb - tb, tb);
            }
        }
        g_sino[b][ang][j] = S * expf(-2.0f * A);   // VOXEL_MM = 2
    }
}

// ---------------------------------------------------------------------------
// Per-angle 5-tap detector blur (reflect) + per-batch scale -> output.
__global__ void sino_blur(const float* __restrict__ scale, float* __restrict__ out) {
    int ang = blockIdx.x;
    int b   = blockIdx.y;
    __shared__ float row[ND];
    __shared__ float k[5];
    for (int i = threadIdx.x; i < ND; i += blockDim.x) row[i] = g_sino[b][ang][i];
    if (threadIdx.x < 5) k[threadIdx.x] = g_ks[ang][threadIdx.x];
    __syncthreads();
    int j = threadIdx.x;
    if (j < ND) {
        float acc = 0.f;
#pragma unroll
        for (int d = -2; d <= 2; ++d) {
            int idx = j + d;
            idx = idx < 0 ? -idx : (idx > ND - 1 ? 2 * (ND - 1) - idx : idx);
            acc = fmaf(k[d + 2], row[idx], acc);
        }
        out[(b * NA + ang) * ND + j] = acc * scale[b];
    }
}

// ---------------------------------------------------------------------------
extern "C" void kernel_launch(void* const* d_in, const int* in_sizes, int n_in,
                              void* d_out, int out_size) {
    const float* img   = (const float*)d_in[0];
    const float* att   = (const float*)d_in[1];
    const float* scale = (const float*)d_in[2];
    float* out = (float*)d_out;
    (void)in_sizes; (void)n_in; (void)out_size;

    cudaFuncSetAttribute(radon_kernel, cudaFuncAttributeMaxDynamicSharedMemorySize,
                         TS * TSTRIDE * (int)sizeof(float2));

    init_kernel<<<1, 320>>>();
    int nH = NB * 128 * TS;
    blur_h<<<(nH + 255) / 256, 256>>>(img, att);
    int nV = NB * TS * TS;
    blur_v<<<(nV + 255) / 256, 256>>>();
    radon_kernel<<<dim3(NA / G_ANG, NB), 640, TS * TSTRIDE * sizeof(float2)>>>();
    sino_blur<<<dim3(NA, NB), 320>>>(scale, out);
}

// round 3
// speedup vs baseline: 1.3741x; 1.3741x over previous
#include <cuda_runtime.h>
#include <cuda_fp16.h>
#include <math.h>

// ---------------------------------------------------------------------------
// PET forward, round 3:
//  - prep kernel (1 block/batch): H+V Gaussian blur (9/17-tap) of emission &
//    attenuation through smem, output as fp16 x-duplicated records:
//    g_tile[b][y][x] = (half2(e[x],a[x]), half2(e[x+1],a[x+1]))  [8 bytes]
//  - radon kernel (block = 4 angles x batch): stage records in smem with
//    XOR-15 swizzle; each thread walks a clipped line with ONE LDS.64 per
//    bilinear row, interpolates both channels in half2, accumulates fp32.
//    Epilogue (same kernel, via smem rows): attenuation-corrected value,
//    per-angle 5-tap reflect detector blur, per-batch scale, write output.
// ---------------------------------------------------------------------------

#define NB 16
#define NA 300
#define ND 300
#define TS 148        // support tile (canvas rows/cols 76..223)
#define SMS 160       // smem row stride in 8B records (mult of 16 for swizzle)
#define G_ANG 4
#define RBLK 640

#define TILE_BYTES (TS * SMS * 8)                 // 189440
#define RAD_SMEM   (TILE_BYTES + G_ANG * ND * 4)  // + sinogram rows

__device__ uint2 g_tile[NB][TS][TS];   // fp16 dup-packed records

// ---------------------------------------------------------------------------
// prep: one block per batch. Blur H -> smem, blur V -> fp16 records.
__global__ __launch_bounds__(1024, 1) void prep_kernel(
        const float* __restrict__ img, const float* __restrict__ att) {
    extern __shared__ float2 Hs[];          // [128][TS]
    __shared__ float K4[9], K8[17];
    int b = blockIdx.x, tid = threadIdx.x;

    if (tid == 0) {
        const float sig_i = 1.2011224087864498f;   // 1/sqrt(ln2)
        const float sig_a = 2.4022448175728997f;   // 2/sqrt(ln2)
        float w4[9], s4 = 0.f, w8[17], s8 = 0.f;
        for (int d = -4; d <= 4; ++d) { float w = expf(-0.5f*(d/sig_i)*(d/sig_i)); w4[d+4] = w; s4 += w; }
        for (int i = 0; i < 9; ++i) K4[i] = w4[i] / s4;
        for (int d = -8; d <= 8; ++d) { float w = expf(-0.5f*(d/sig_a)*(d/sig_a)); w8[d+8] = w; s8 += w; }
        for (int i = 0; i < 17; ++i) K8[i] = w8[i] / s8;
    }
    __syncthreads();

    // Horizontal pass: input rows y in [0,128), tile cols c in [0,TS)
    const float* ib = img + b * 128 * 128;
    const float* ab = att + b * 128 * 128;
    for (int idx = tid; idx < 128 * TS; idx += blockDim.x) {
        int c = idx % TS, y = idx / TS;
        int xc = c - 10;
        float a0 = 0.f, a1 = 0.f;
        const float* ir = ib + y * 128;
        const float* ar = ab + y * 128;
#pragma unroll
        for (int d = -8; d <= 8; ++d) {
            int xi = xc + d;
            if (xi >= 0 && xi < 128) {
                a1 += K8[d + 8] * ar[xi];
                if (d >= -4 && d <= 4) a0 += K4[d + 4] * ir[xi];
            }
        }
        Hs[idx] = make_float2(a0, a1);
    }
    __syncthreads();

    // Vertical pass -> fp16 records (lo slot at c, hi slot at c-1)
    unsigned* gt = (unsigned*)&g_tile[b][0][0];
    for (int idx = tid; idx < TS * TS; idx += blockDim.x) {
        int c = idx % TS, r = idx / TS;
        int yc = r - 10;
        float a0 = 0.f, a1 = 0.f;
#pragma unroll
        for (int d = -8; d <= 8; ++d) {
            int yi = yc + d;
            if (yi >= 0 && yi < 128) {
                float2 t = Hs[yi * TS + c];
                a1 += K8[d + 8] * t.y;
                if (d >= -4 && d <= 4) a0 += K4[d + 4] * t.x;
            }
        }
        __half2 h = __floats2half2_rn(a0, a1 * 0.01f);
        unsigned u = *(unsigned*)&h;
        gt[(r * TS + c) * 2 + 0] = u;                    // lo slot of record c
        if (c > 0)   gt[(r * TS + c - 1) * 2 + 1] = u;   // hi slot of record c-1
        if (c == TS - 1) gt[(r * TS + c) * 2 + 1] = 0;   // hi of last record
    }
}

// ---------------------------------------------------------------------------
__global__ __launch_bounds__(RBLK, 1) void radon_kernel(
        const float* __restrict__ scale, float* __restrict__ out) {
    extern __shared__ char dyn[];
    uint2* tile = (uint2*)dyn;
    float* srow = (float*)(dyn + TILE_BYTES);   // [G_ANG][ND]

    int b    = blockIdx.y;
    int ang0 = blockIdx.x * G_ANG;
    int tid  = threadIdx.x;

    // Stage tile with XOR-15 swizzle on record column
    const uint2* gt = &g_tile[b][0][0];
    for (int i = tid; i < TS * TS; i += RBLK) {
        int y = i / TS, x = i - y * TS;
        tile[y * SMS + (x ^ (y & 15))] = gt[i];
    }
    __syncthreads();

    const int items = G_ANG * ND;
    for (int it = tid; it < items; it += RBLK) {
        int al  = it / ND;
        int j   = it - al * ND;
        int ang = ang0 + al;
        float th  = (float)ang * 0.6020066889632107f;     // *180/299
        float rad = th * 0.017453292519943295f;
        float s, c;
        sincosf(rad, &s, &c);
        float u  = (float)j - 149.5f;
        float bx = fmaf(c,  u, fmaf(-149.5f, s, 73.5f));
        float by = fmaf(-s, u, fmaf(-149.5f, c, 73.5f));

        const float LO = 0.999f, HI = 146.001f;
        float t0 = 0.f, t1 = 299.f;
        bool empty = false;
        if (fabsf(s) > 1e-6f) {
            float ra = (LO - bx) / s, rb = (HI - bx) / s;
            t0 = fmaxf(t0, fminf(ra, rb));
            t1 = fminf(t1, fmaxf(ra, rb));
        } else if (bx <= LO || bx >= HI) empty = true;
        if (fabsf(c) > 1e-6f) {
            float ra = (LO - by) / c, rb = (HI - by) / c;
            t0 = fmaxf(t0, fminf(ra, rb));
            t1 = fminf(t1, fmaxf(ra, rb));
        } else if (by <= LO || by >= HI) empty = true;

        float S = 0.f, A = 0.f;
        if (!empty && t0 <= t1) {
            int i0 = (int)ceilf(t0);  if (i0 < 0)   i0 = 0;
            int i1 = (int)floorf(t1); if (i1 > 299) i1 = 299;
            int n  = i1 - i0 + 1;
            float lx = fmaf(s, (float)i0, bx);
            float ly = fmaf(c, (float)i0, by);
#pragma unroll 2
            for (int k = 0; k < n; ++k) {
                int x0 = __float2int_rd(lx);
                int y0 = __float2int_rd(ly);
                float wx = lx - (float)x0;
                float wy = ly - (float)y0;
                __half2 wx2 = __float2half2_rn(wx);
                __half2 wy2 = __float2half2_rn(wy);
                int y1 = y0 + 1;
                int c0 = x0 ^ (y0 & 15);
                int c1 = x0 ^ (y1 & 15);
                uint2 q0 = tile[y0 * SMS + c0];
                uint2 q1 = tile[y1 * SMS + c1];
                __half2 v00 = *(__half2*)&q0.x, v01 = *(__half2*)&q0.y;
                __half2 v10 = *(__half2*)&q1.x, v11 = *(__half2*)&q1.y;
                __half2 r0h = __hfma2(wx2, __hsub2(v01, v00), v00);
                __half2 r1h = __hfma2(wx2, __hsub2(v11, v10), v10);
                __half2 rr  = __hfma2(wy2, __hsub2(r1h, r0h), r0h);
                float2 rf = __half22float2(rr);
                S += rf.x;
                A += rf.y;
                lx += s;
                ly += c;
            }
        }
        srow[al * ND + j] = S * expf(-2.0f * A);   // VOXEL_MM = 2
    }
    __syncthreads();

    // Fused per-angle 5-tap detector blur (reflect) + per-batch scale
    float sc = scale[b];
    for (int it = tid; it < items; it += RBLK) {
        int al  = it / ND;
        int j   = it - al * ND;
        int ang = ang0 + al;
        float th  = (float)ang * 0.6020066889632107f;
        float rad = th * 0.017453292519943295f;
        float s, c;
        sincosf(rad, &s, &c);
        float bw = 2.0f * (fabsf(c) + fabsf(s));
        float q  = 0.34657359027997264f * bw * bw;     // 0.5*ln2*bw^2 = 0.5/sig^2
        float e1 = expf(-q);
        float e2 = expf(-4.0f * q);
        float norm = 1.0f / (1.0f + 2.0f * e1 + 2.0f * e2);
        const float* row = srow + al * ND;
        int jm2 = j - 2; jm2 = jm2 < 0 ? -jm2 : jm2;
        int jm1 = j - 1; jm1 = jm1 < 0 ? -jm1 : jm1;
        int jp1 = j + 1; jp1 = jp1 > ND - 1 ? 2 * (ND - 1) - jp1 : jp1;
        int jp2 = j + 2; jp2 = jp2 > ND - 1 ? 2 * (ND - 1) - jp2 : jp2;
        float acc = row[j]
                  + e1 * (row[jm1] + row[jp1])
                  + e2 * (row[jm2] + row[jp2]);
        out[(b * NA + ang) * ND + j] = acc * norm * sc;
    }
}

// ---------------------------------------------------------------------------
extern "C" void kernel_launch(void* const* d_in, const int* in_sizes, int n_in,
                              void* d_out, int out_size) {
    const float* img   = (const float*)d_in[0];
    const float* att   = (const float*)d_in[1];
    const float* scale = (const float*)d_in[2];
    float* out = (float*)d_out;
    (void)in_sizes; (void)n_in; (void)out_size;

    static int attr_done = 0;
    cudaFuncSetAttribute(prep_kernel,  cudaFuncAttributeMaxDynamicSharedMemorySize,
                         128 * TS * (int)sizeof(float2));
    cudaFuncSetAttribute(radon_kernel, cudaFuncAttributeMaxDynamicSharedMemorySize,
                         RAD_SMEM);
    (void)attr_done;

    prep_kernel<<<NB, 1024, 128 * TS * sizeof(float2)>>>(img, att);
    radon_kernel<<<dim3(NA / G_ANG, NB), RBLK, RAD_SMEM>>>(scale, out);
}

// round 4
// speedup vs baseline: 1.7130x; 1.2466x over previous
#include <cuda_runtime.h>
#include <cuda_fp16.h>
#include <math.h>

// ---------------------------------------------------------------------------
// PET forward, round 4:
//  - prep (64 blocks, column-split): H+V Gaussian blur -> fp16 x-dup records
//  - radon (block = 12 angles x batch, 1024 thr): smem tile, XOR swizzle,
//    magic-float floor, one LDS.64 per bilinear row, half2 interp, pairwise
//    fp16 accumulation; fused attenuation + detector blur + scale epilogue.
// ---------------------------------------------------------------------------

#define NB 16
#define NA 300
#define ND 300
#define TS 148        // support tile (canvas rows/cols 76..223)
#define SMS 160       // smem row stride in 8B records (mult of 16 for swizzle)
#define G_ANG 12
#define RBLK 1024
#define CPB 37        // tile cols per prep block (148/4)

#define TILE_BYTES (TS * SMS * 8)                 // 189440
#define RAD_SMEM   (TILE_BYTES + G_ANG * ND * 4)  // 203840

__device__ uint2 g_tile[NB][TS][TS];   // fp16 dup-packed records

// ---------------------------------------------------------------------------
// prep: grid (4, NB). Each block owns CPB tile columns; H pass feeds V pass
// column-aligned, so no cross-block dependency.
__global__ __launch_bounds__(512, 2) void prep_kernel(
        const float* __restrict__ img, const float* __restrict__ att) {
    extern __shared__ float2 Hs[];          // [128][CPB]
    __shared__ float K4[9], K8[17];
    int b  = blockIdx.y;
    int c0 = blockIdx.x * CPB;
    int tid = threadIdx.x;

    if (tid == 0) {
        const float sig_i = 1.2011224087864498f;   // 1/sqrt(ln2)
        const float sig_a = 2.4022448175728997f;   // 2/sqrt(ln2)
        float w4[9], s4 = 0.f, w8[17], s8 = 0.f;
        for (int d = -4; d <= 4; ++d) { float w = expf(-0.5f*(d/sig_i)*(d/sig_i)); w4[d+4] = w; s4 += w; }
        for (int i = 0; i < 9; ++i) K4[i] = w4[i] / s4;
        for (int d = -8; d <= 8; ++d) { float w = expf(-0.5f*(d/sig_a)*(d/sig_a)); w8[d+8] = w; s8 += w; }
        for (int i = 0; i < 17; ++i) K8[i] = w8[i] / s8;
    }
    __syncthreads();

    const float* ib = img + b * 128 * 128;
    const float* ab = att + b * 128 * 128;
    for (int idx = tid; idx < 128 * CPB; idx += blockDim.x) {
        int cl = idx % CPB, y = idx / CPB;
        int xc = c0 + cl - 10;
        float a0 = 0.f, a1 = 0.f;
        const float* ir = ib + y * 128;
        const float* ar = ab + y * 128;
#pragma unroll
        for (int d = -8; d <= 8; ++d) {
            int xi = xc + d;
            if (xi >= 0 && xi < 128) {
                a1 += K8[d + 8] * ar[xi];
                if (d >= -4 && d <= 4) a0 += K4[d + 4] * ir[xi];
            }
        }
        Hs[idx] = make_float2(a0, a1);
    }
    __syncthreads();

    unsigned* gt = (unsigned*)&g_tile[b][0][0];
    for (int idx = tid; idx < TS * CPB; idx += blockDim.x) {
        int cl = idx % CPB, r = idx / CPB;
        int c  = c0 + cl;
        int yc = r - 10;
        float a0 = 0.f, a1 = 0.f;
#pragma unroll
        for (int d = -8; d <= 8; ++d) {
            int yi = yc + d;
            if (yi >= 0 && yi < 128) {
                float2 t = Hs[yi * CPB + cl];
                a1 += K8[d + 8] * t.y;
                if (d >= -4 && d <= 4) a0 += K4[d + 4] * t.x;
            }
        }
        __half2 h = __floats2half2_rn(a0, a1 * 0.01f);
        unsigned u = *(unsigned*)&h;
        gt[(r * TS + c) * 2 + 0] = u;                    // lo slot of record c
        if (c > 0)       gt[(r * TS + c - 1) * 2 + 1] = u;  // hi slot of record c-1
        if (c == TS - 1) gt[(r * TS + c) * 2 + 1] = 0;      // hi of last record
    }
}

// ---------------------------------------------------------------------------
#define MAGF 8388608.0f   // 2^23: add.rz then subtract gives floor for x>=0

__global__ __launch_bounds__(RBLK, 1) void radon_kernel(
        const float* __restrict__ scale, float* __restrict__ out) {
    extern __shared__ char dyn[];
    uint2* tile = (uint2*)dyn;
    float* srow = (float*)(dyn + TILE_BYTES);   // [G_ANG][ND]

    int b    = blockIdx.y;
    int ang0 = blockIdx.x * G_ANG;
    int tid  = threadIdx.x;

    const uint2* gt = &g_tile[b][0][0];
    for (int i = tid; i < TS * TS; i += RBLK) {
        int y = i / TS, x = i - y * TS;
        tile[y * SMS + (x ^ (y & 15))] = gt[i];
    }
    __syncthreads();

    auto samp = [&](float lx, float ly) -> __half2 {
        float fxm = __fadd_rz(lx, MAGF);
        float fym = __fadd_rz(ly, MAGF);
        float wx  = lx - (fxm - MAGF);
        float wy  = ly - (fym - MAGF);
        int xb = __float_as_int(fxm);
        int yb = __float_as_int(fym);
        int x0 = xb & 0xFFFFFF;
        int y0 = yb & 0xFFFFFF;
        int m0 = yb & 15;
        int m1 = (yb + 1) & 15;
        int r0 = y0 * SMS;
        uint2 q0 = tile[r0 + (x0 ^ m0)];
        uint2 q1 = tile[r0 + SMS + (x0 ^ m1)];
        __half2 wx2 = __float2half2_rn(wx);
        __half2 wy2 = __float2half2_rn(wy);
        __half2 v00 = *(__half2*)&q0.x, v01 = *(__half2*)&q0.y;
        __half2 v10 = *(__half2*)&q1.x, v11 = *(__half2*)&q1.y;
        __half2 r0h = __hfma2(wx2, __hsub2(v01, v00), v00);
        __half2 r1h = __hfma2(wx2, __hsub2(v11, v10), v10);
        return __hfma2(wy2, __hsub2(r1h, r0h), r0h);
    };

    const int items = G_ANG * ND;
    for (int it = tid; it < items; it += RBLK) {
        int al  = it / ND;
        int j   = it - al * ND;
        int ang = ang0 + al;
        float th  = (float)ang * 0.6020066889632107f;     // *180/299
        float rad = th * 0.017453292519943295f;
        float s, c;
        sincosf(rad, &s, &c);
        float u  = (float)j - 149.5f;
        float bx = fmaf(c,  u, fmaf(-149.5f, s, 73.5f));
        float by = fmaf(-s, u, fmaf(-149.5f, c, 73.5f));

        const float LO = 0.999f, HI = 146.001f;
        float t0 = 0.f, t1 = 299.f;
        bool empty = false;
        if (fabsf(s) > 1e-6f) {
            float ra = (LO - bx) / s, rb = (HI - bx) / s;
            t0 = fmaxf(t0, fminf(ra, rb));
            t1 = fminf(t1, fmaxf(ra, rb));
        } else if (bx <= LO || bx >= HI) empty = true;
        if (fabsf(c) > 1e-6f) {
            float ra = (LO - by) / c, rb = (HI - by) / c;
            t0 = fmaxf(t0, fminf(ra, rb));
            t1 = fminf(t1, fmaxf(ra, rb));
        } else if (by <= LO || by >= HI) empty = true;

        float S = 0.f, A = 0.f;
        if (!empty && t0 <= t1) {
            int i0 = (int)ceilf(t0);  if (i0 < 0)   i0 = 0;
            int i1 = (int)floorf(t1); if (i1 > 299) i1 = 299;
            int n  = i1 - i0 + 1;
            float lxa = fmaf(s, (float)i0, bx);
            float lya = fmaf(c, (float)i0, by);
            float lxb = lxa + s, lyb = lya + c;
            float s2 = s + s, c2 = c + c;
            int k = 0;
#pragma unroll 1
            for (; k + 1 < n; k += 2) {
                __half2 ra = samp(lxa, lya);
                __half2 rb = samp(lxb, lyb);
                __half2 rc = __hadd2(ra, rb);
                float2 f = __half22float2(rc);
                S += f.x; A += f.y;
                lxa += s2; lya += c2;
                lxb += s2; lyb += c2;
            }
            if (k < n) {
                float2 f = __half22float2(samp(lxa, lya));
                S += f.x; A += f.y;
            }
        }
        srow[al * ND + j] = S * expf(-2.0f * A);   // VOXEL_MM = 2
    }
    __syncthreads();

    // Fused per-angle 5-tap detector blur (reflect) + per-batch scale
    float sc = scale[b];
    for (int it = tid; it < items; it += RBLK) {
        int al  = it / ND;
        int j   = it - al * ND;
        int ang = ang0 + al;
        float th  = (float)ang * 0.6020066889632107f;
        float rad = th * 0.017453292519943295f;
        float s, c;
        sincosf(rad, &s, &c);
        float bw = 2.0f * (fabsf(c) + fabsf(s));
        float q  = 0.34657359027997264f * bw * bw;     // 0.5*ln2*bw^2
        float e1 = expf(-q);
        float e2 = expf(-4.0f * q);
        float norm = 1.0f / (1.0f + 2.0f * e1 + 2.0f * e2);
        const float* row = srow + al * ND;
        int jm2 = j - 2; jm2 = jm2 < 0 ? -jm2 : jm2;
        int jm1 = j - 1; jm1 = jm1 < 0 ? -jm1 : jm1;
        int jp1 = j + 1; jp1 = jp1 > ND - 1 ? 2 * (ND - 1) - jp1 : jp1;
        int jp2 = j + 2; jp2 = jp2 > ND - 1 ? 2 * (ND - 1) - jp2 : jp2;
        float acc = row[j]
                  + e1 * (row[jm1] + row[jp1])
                  + e2 * (row[jm2] + row[jp2]);
        out[(b * NA + ang) * ND + j] = acc * norm * sc;
    }
}

// ---------------------------------------------------------------------------
extern "C" void kernel_launch(void* const* d_in, const int* in_sizes, int n_in,
                              void* d_out, int out_size) {
    const float* img   = (const float*)d_in[0];
    const float* att   = (const float*)d_in[1];
    const float* scale = (const float*)d_in[2];
    float* out = (float*)d_out;
    (void)in_sizes; (void)n_in; (void)out_size;

    cudaFuncSetAttribute(prep_kernel,  cudaFuncAttributeMaxDynamicSharedMemorySize,
                         128 * CPB * (int)sizeof(float2));
    cudaFuncSetAttribute(radon_kernel, cudaFuncAttributeMaxDynamicSharedMemorySize,
                         RAD_SMEM);

    prep_kernel<<<dim3(4, NB), 512, 128 * CPB * sizeof(float2)>>>(img, att);
    radon_kernel<<<dim3(NA / G_ANG, NB), RBLK, RAD_SMEM>>>(scale, out);
}

// round 5
// speedup vs baseline: 1.9522x; 1.1396x over previous
#include <cuda_runtime.h>
#include <cuda_fp16.h>
#include <math.h>

// ---------------------------------------------------------------------------
// PET forward, round 5:
//  - prep (64 blocks, column-split): H+V Gaussian blur -> fp16 x-dup records
//  - radon: persistent one-wave grid (9 angle-ranges x 16 batches). Tile
//    staged ONCE per block; angles processed in chunks of 12 with fused
//    attenuation + detector-blur + scale epilogue per chunk.
//    Bias-cancel magic-float addressing, one LDS.64 per bilinear row,
//    half2 interpolation, quad fp16 accumulation.
// ---------------------------------------------------------------------------

#define NB 16
#define NA 300
#define ND 300
#define TS 148        // support tile (canvas rows/cols 76..223)
#define SMS 160       // smem row stride in 8B records (mult of 16 for swizzle)
#define NBLK 9        // angle-range blocks per batch (one-wave: 9*16=144)
#define CHUNK 12      // angles per epilogue chunk
#define RBLK 1024
#define CPB 37        // tile cols per prep block (148/4)

#define TILE_BYTES (TS * SMS * 8)                 // 189440
#define RAD_SMEM   (TILE_BYTES + CHUNK * ND * 4)  // 203840

__device__ uint2 g_tile[NB][TS][TS];   // fp16 dup-packed records

// ---------------------------------------------------------------------------
__global__ __launch_bounds__(512, 2) void prep_kernel(
        const float* __restrict__ img, const float* __restrict__ att) {
    extern __shared__ float2 Hs[];          // [128][CPB]
    __shared__ float K4[9], K8[17];
    int b  = blockIdx.y;
    int c0 = blockIdx.x * CPB;
    int tid = threadIdx.x;

    if (tid == 0) {
        const float sig_i = 1.2011224087864498f;   // 1/sqrt(ln2)
        const float sig_a = 2.4022448175728997f;   // 2/sqrt(ln2)
        float w4[9], s4 = 0.f, w8[17], s8 = 0.f;
        for (int d = -4; d <= 4; ++d) { float w = expf(-0.5f*(d/sig_i)*(d/sig_i)); w4[d+4] = w; s4 += w; }
        for (int i = 0; i < 9; ++i) K4[i] = w4[i] / s4;
        for (int d = -8; d <= 8; ++d) { float w = expf(-0.5f*(d/sig_a)*(d/sig_a)); w8[d+8] = w; s8 += w; }
        for (int i = 0; i < 17; ++i) K8[i] = w8[i] / s8;
    }
    __syncthreads();

    const float* ib = img + b * 128 * 128;
    const float* ab = att + b * 128 * 128;
    for (int idx = tid; idx < 128 * CPB; idx += blockDim.x) {
        int cl = idx % CPB, y = idx / CPB;
        int xc = c0 + cl - 10;
        float a0 = 0.f, a1 = 0.f;
        const float* ir = ib + y * 128;
        const float* ar = ab + y * 128;
#pragma unroll
        for (int d = -8; d <= 8; ++d) {
            int xi = xc + d;
            if (xi >= 0 && xi < 128) {
                a1 += K8[d + 8] * ar[xi];
                if (d >= -4 && d <= 4) a0 += K4[d + 4] * ir[xi];
            }
        }
        Hs[idx] = make_float2(a0, a1);
    }
    __syncthreads();

    unsigned* gt = (unsigned*)&g_tile[b][0][0];
    for (int idx = tid; idx < TS * CPB; idx += blockDim.x) {
        int cl = idx % CPB, r = idx / CPB;
        int c  = c0 + cl;
        int yc = r - 10;
        float a0 = 0.f, a1 = 0.f;
#pragma unroll
        for (int d = -8; d <= 8; ++d) {
            int yi = yc + d;
            if (yi >= 0 && yi < 128) {
                float2 t = Hs[yi * CPB + cl];
                a1 += K8[d + 8] * t.y;
                if (d >= -4 && d <= 4) a0 += K4[d + 4] * t.x;
            }
        }
        __half2 h = __floats2half2_rn(a0, a1 * 0.01f);
        unsigned u = *(unsigned*)&h;
        gt[(r * TS + c) * 2 + 0] = u;                      // lo slot of record c
        if (c > 0)       gt[(r * TS + c - 1) * 2 + 1] = u; // hi slot of record c-1
        if (c == TS - 1) gt[(r * TS + c) * 2 + 1] = 0;     // hi of last record
    }
}

// ---------------------------------------------------------------------------
#define MAGF 8388608.0f   // 2^23
// bias constant folded out of (yb*SMS + (xb^m))*8 byte addressing
#define KADJ (0x4B000000u * (unsigned)(SMS * 8) + 0x4B000000u * 8u)

__global__ __launch_bounds__(RBLK, 1) void radon_kernel(
        const float* __restrict__ scale, float* __restrict__ out) {
    extern __shared__ char dyn[];
    char*  tileb = dyn;
    float* srow  = (float*)(dyn + TILE_BYTES);   // [CHUNK][ND]

    int b   = blockIdx.y;
    int blk = blockIdx.x;                 // 0..NBLK-1 angle range
    int tid = threadIdx.x;

    // Stage tile once (XOR swizzle on record column)
    {
        uint2* tile = (uint2*)tileb;
        const uint2* gt = &g_tile[b][0][0];
        for (int i = tid; i < TS * TS; i += RBLK) {
            int y = i / TS, x = i - y * TS;
            tile[y * SMS + (x ^ (y & 15))] = gt[i];
        }
    }
    __syncthreads();

    auto samp = [&](float lx, float ly) -> __half2 {
        float fxm = __fadd_rz(lx, MAGF);
        float fym = __fadd_rz(ly, MAGF);
        float wx  = lx - (fxm - MAGF);
        float wy  = ly - (fym - MAGF);
        unsigned xb = __float_as_uint(fxm);
        unsigned yb = __float_as_uint(fym);
        unsigned m0 = yb & 15u;
        unsigned m1 = (yb + 1u) & 15u;
        unsigned off0 = yb * (SMS * 8u) + ((xb ^ m0) << 3) - KADJ;
        unsigned off1 = yb * (SMS * 8u) + ((xb ^ m1) << 3) - (KADJ - SMS * 8u);
        uint2 q0 = *(const uint2*)(tileb + off0);
        uint2 q1 = *(const uint2*)(tileb + off1);
        __half2 wx2 = __float2half2_rn(wx);
        __half2 wy2 = __float2half2_rn(wy);
        __half2 v00 = *(__half2*)&q0.x, v01 = *(__half2*)&q0.y;
        __half2 v10 = *(__half2*)&q1.x, v11 = *(__half2*)&q1.y;
        __half2 r0h = __hfma2(wx2, __hsub2(v01, v00), v00);
        __half2 r1h = __hfma2(wx2, __hsub2(v11, v10), v10);
        return __hfma2(wy2, __hsub2(r1h, r0h), r0h);
    };

    int aStart = (blk * NA) / NBLK;
    int aEnd   = ((blk + 1) * NA) / NBLK;
    float sc = scale[b];

    for (int ang0 = aStart; ang0 < aEnd; ang0 += CHUNK) {
        int na = aEnd - ang0; if (na > CHUNK) na = CHUNK;
        int items = na * ND;

        for (int it = tid; it < items; it += RBLK) {
            int al  = it / ND;
            int j   = it - al * ND;
            int ang = ang0 + al;
            float th  = (float)ang * 0.6020066889632107f;     // *180/299
            float rad = th * 0.017453292519943295f;
            float s, c;
            sincosf(rad, &s, &c);
            float u  = (float)j - 149.5f;
            float bx = fmaf(c,  u, fmaf(-149.5f, s, 73.5f));
            float by = fmaf(-s, u, fmaf(-149.5f, c, 73.5f));

            const float LO = 0.999f, HI = 146.001f;
            float t0 = 0.f, t1 = 299.f;
            bool empty = false;
            if (fabsf(s) > 1e-6f) {
                float ra = (LO - bx) / s, rb = (HI - bx) / s;
                t0 = fmaxf(t0, fminf(ra, rb));
                t1 = fminf(t1, fmaxf(ra, rb));
            } else if (bx <= LO || bx >= HI) empty = true;
            if (fabsf(c) > 1e-6f) {
                float ra = (LO - by) / c, rb = (HI - by) / c;
                t0 = fmaxf(t0, fminf(ra, rb));
                t1 = fminf(t1, fmaxf(ra, rb));
            } else if (by <= LO || by >= HI) empty = true;

            float S = 0.f, A = 0.f;
            if (!empty && t0 <= t1) {
                int i0 = (int)ceilf(t0);  if (i0 < 0)   i0 = 0;
                int i1 = (int)floorf(t1); if (i1 > 299) i1 = 299;
                int n  = i1 - i0 + 1;
                float lxa = fmaf(s, (float)i0, bx);
                float lya = fmaf(c, (float)i0, by);
                float lxb = lxa + s, lyb = lya + c;
                float s2 = s + s, c2 = c + c;
                int k = 0;
#pragma unroll 1
                for (; k + 3 < n; k += 4) {     // quad: 2 pairs, one convert
                    __half2 ra = samp(lxa, lya);
                    __half2 rb = samp(lxb, lyb);
                    lxa += s2; lya += c2; lxb += s2; lyb += c2;
                    __half2 rc = samp(lxa, lya);
                    __half2 rd = samp(lxb, lyb);
                    lxa += s2; lya += c2; lxb += s2; lyb += c2;
                    __half2 q  = __hadd2(__hadd2(ra, rb), __hadd2(rc, rd));
                    float2 f = __half22float2(q);
                    S += f.x; A += f.y;
                }
                if (k + 1 < n) {                // leftover pair
                    __half2 ra = samp(lxa, lya);
                    __half2 rb = samp(lxb, lyb);
                    __half2 q  = __hadd2(ra, rb);
                    float2 f = __half22float2(q);
                    S += f.x; A += f.y;
                    lxa += s2; lya += c2;
                    k += 2;
                }
                if (k < n) {                    // leftover single
                    float2 f = __half22float2(samp(lxa, lya));
                    S += f.x; A += f.y;
                }
            }
            srow[al * ND + j] = S * expf(-2.0f * A);   // VOXEL_MM = 2
        }
        __syncthreads();

        // Fused per-angle 5-tap detector blur (reflect) + per-batch scale
        for (int it = tid; it < items; it += RBLK) {
            int al  = it / ND;
            int j   = it - al * ND;
            int ang = ang0 + al;
            float th  = (float)ang * 0.6020066889632107f;
            float rad = th * 0.017453292519943295f;
            float s, c;
            sincosf(rad, &s, &c);
            float bw = 2.0f * (fabsf(c) + fabsf(s));
            float q  = 0.34657359027997264f * bw * bw;     // 0.5*ln2*bw^2
            float e1 = expf(-q);
            float e2 = expf(-4.0f * q);
            float norm = 1.0f / (1.0f + 2.0f * e1 + 2.0f * e2);
            const float* row = srow + al * ND;
            int jm2 = j - 2; jm2 = jm2 < 0 ? -jm2 : jm2;
            int jm1 = j - 1; jm1 = jm1 < 0 ? -jm1 : jm1;
            int jp1 = j + 1; jp1 = jp1 > ND - 1 ? 2 * (ND - 1) - jp1 : jp1;
            int jp2 = j + 2; jp2 = jp2 > ND - 1 ? 2 * (ND - 1) - jp2 : jp2;
            float acc = row[j]
                      + e1 * (row[jm1] + row[jp1])
                      + e2 * (row[jm2] + row[jp2]);
            out[(b * NA + ang) * ND + j] = acc * norm * sc;
        }
        __syncthreads();
    }
}

// ---------------------------------------------------------------------------
extern "C" void kernel_launch(void* const* d_in, const int* in_sizes, int n_in,
                              void* d_out, int out_size) {
    const float* img   = (const float*)d_in[0];
    const float* att   = (const float*)d_in[1];
    const float* scale = (const float*)d_in[2];
    float* out = (float*)d_out;
    (void)in_sizes; (void)n_in; (void)out_size;

    cudaFuncSetAttribute(prep_kernel,  cudaFuncAttributeMaxDynamicSharedMemorySize,
                         128 * CPB * (int)sizeof(float2));
    cudaFuncSetAttribute(radon_kernel, cudaFuncAttributeMaxDynamicSharedMemorySize,
                         RAD_SMEM);

    prep_kernel<<<dim3(4, NB), 512, 128 * CPB * sizeof(float2)>>>(img, att);
    radon_kernel<<<dim3(NBLK, NB), RBLK, RAD_SMEM>>>(scale, out);
}

// round 6
// speedup vs baseline: 2.0093x; 1.0293x over previous
#include <cuda_runtime.h>
#include <cuda_fp16.h>
#include <math.h>

// ---------------------------------------------------------------------------
// PET forward, round 6:
//  - prep (64 blocks, column-split): H+V Gaussian blur -> fp16 x-dup records
//  - radon: one-wave persistent grid (9 x 16). Tile staged once per block.
//    NEW: packed f32x2 walkers (add.rn.f32x2 / fma.rn.f32x2): one 64-bit
//    register carries (lx-0.5, ly-0.5); magic-rn floor + weight extraction
//    in 4 packed ops + 1 packed update (vs 8 scalar FADDs). Integer coords
//    come free from the magic-result register halves (bias-cancel addr).
//    Half2 bilinear, quad fp16 accumulation, fused epilogue.
// ---------------------------------------------------------------------------

#define NB 16
#define NA 300
#define ND 300
#define TS 148
#define SMS 160
#define NBLK 9
#define CHUNK 12
#define RBLK 1024
#define CPB 37

#define TILE_BYTES (TS * SMS * 8)
#define RAD_SMEM   (TILE_BYTES + CHUNK * ND * 4)

__device__ uint2 g_tile[NB][TS][TS];

// ---- packed f32x2 helpers --------------------------------------------------
#define ADD2(d,a,b)   asm("add.rn.f32x2 %0, %1, %2;" : "=l"(d) : "l"(a), "l"(b))
#define FMA2(d,a,b,c) asm("fma.rn.f32x2 %0, %1, %2, %3;" : "=l"(d) : "l"(a), "l"(b), "l"(c))

__device__ __forceinline__ unsigned long long pk2(float a, float b) {
    unsigned long long r;
    asm("mov.b64 %0, {%1, %2};" : "=l"(r) : "f"(a), "f"(b));
    return r;
}
__device__ __forceinline__ void upk_u(unsigned long long a, unsigned& lo, unsigned& hi) {
    asm("mov.b64 {%0, %1}, %2;" : "=r"(lo), "=r"(hi) : "l"(a));
}
__device__ __forceinline__ void upk_f(unsigned long long a, float& lo, float& hi) {
    asm("mov.b64 {%0, %1}, %2;" : "=f"(lo), "=f"(hi) : "l"(a));
}

// ---------------------------------------------------------------------------
__global__ __launch_bounds__(512, 2) void prep_kernel(
        const float* __restrict__ img, const float* __restrict__ att) {
    extern __shared__ float2 Hs[];          // [128][CPB]
    __shared__ float K4[9], K8[17];
    int b  = blockIdx.y;
    int c0 = blockIdx.x * CPB;
    int tid = threadIdx.x;

    if (tid == 0) {
        const float sig_i = 1.2011224087864498f;
        const float sig_a = 2.4022448175728997f;
        float w4[9], s4 = 0.f, w8[17], s8 = 0.f;
        for (int d = -4; d <= 4; ++d) { float w = expf(-0.5f*(d/sig_i)*(d/sig_i)); w4[d+4] = w; s4 += w; }
        for (int i = 0; i < 9; ++i) K4[i] = w4[i] / s4;
        for (int d = -8; d <= 8; ++d) { float w = expf(-0.5f*(d/sig_a)*(d/sig_a)); w8[d+8] = w; s8 += w; }
        for (int i = 0; i < 17; ++i) K8[i] = w8[i] / s8;
    }
    __syncthreads();

    const float* ib = img + b * 128 * 128;
    const float* ab = att + b * 128 * 128;
    for (int idx = tid; idx < 128 * CPB; idx += blockDim.x) {
        int cl = idx % CPB, y = idx / CPB;
        int xc = c0 + cl - 10;
        float a0 = 0.f, a1 = 0.f;
        const float* ir = ib + y * 128;
        const float* ar = ab + y * 128;
#pragma unroll
        for (int d = -8; d <= 8; ++d) {
            int xi = xc + d;
            if (xi >= 0 && xi < 128) {
                a1 += K8[d + 8] * ar[xi];
                if (d >= -4 && d <= 4) a0 += K4[d + 4] * ir[xi];
            }
        }
        Hs[idx] = make_float2(a0, a1);
    }
    __syncthreads();

    unsigned* gt = (unsigned*)&g_tile[b][0][0];
    for (int idx = tid; idx < TS * CPB; idx += blockDim.x) {
        int cl = idx % CPB, r = idx / CPB;
        int c  = c0 + cl;
        int yc = r - 10;
        float a0 = 0.f, a1 = 0.f;
#pragma unroll
        for (int d = -8; d <= 8; ++d) {
            int yi = yc + d;
            if (yi >= 0 && yi < 128) {
                float2 t = Hs[yi * CPB + cl];
                a1 += K8[d + 8] * t.y;
                if (d >= -4 && d <= 4) a0 += K4[d + 4] * t.x;
            }
        }
        __half2 h = __floats2half2_rn(a0, a1 * 0.01f);
        unsigned u = *(unsigned*)&h;
        gt[(r * TS + c) * 2 + 0] = u;
        if (c > 0)       gt[(r * TS + c - 1) * 2 + 1] = u;
        if (c == TS - 1) gt[(r * TS + c) * 2 + 1] = 0;
    }
}

// ---------------------------------------------------------------------------
#define MAGF 8388608.0f   // 2^23
#define KADJ (0x4B000000u * (unsigned)(SMS * 8) + 0x4B000000u * 8u)

__global__ __launch_bounds__(RBLK, 1) void radon_kernel(
        const float* __restrict__ scale, float* __restrict__ out) {
    extern __shared__ char dyn[];
    char*  tileb = dyn;
    float* srow  = (float*)(dyn + TILE_BYTES);   // [CHUNK][ND]

    int b   = blockIdx.y;
    int blk = blockIdx.x;
    int tid = threadIdx.x;

    {
        uint2* tile = (uint2*)tileb;
        const uint2* gt = &g_tile[b][0][0];
        for (int i = tid; i < TS * TS; i += RBLK) {
            int y = i / TS, x = i - y * TS;
            tile[y * SMS + (x ^ (y & 15))] = gt[i];
        }
    }
    __syncthreads();

    const unsigned long long MAG2  = pk2(MAGF, MAGF);
    const unsigned long long NMAG2 = pk2(-MAGF, -MAGF);
    const unsigned long long NEG12 = pk2(-1.0f, -1.0f);
    const unsigned long long HALF2 = pk2(0.5f, 0.5f);

    // p carries (lx-0.5, ly-0.5). Magic-rn gives r = round(lx-0.5), which is
    // floor(lx) except at exact-integer lx where r = floor-1 and the weight
    // comes out exactly 1.0 — bilinear then returns the exact grid value.
    auto samp = [&](unsigned long long p) -> __half2 {
        unsigned long long fm, t, w, w05;
        ADD2(fm, p, MAG2);          // rn magic: (0x4B000000+rx, 0x4B000000+ry)
        ADD2(t,  fm, NMAG2);        // exact (rx, ry) as floats
        FMA2(w,  t, NEG12, p);      // p - t   (exact, in [-0.5, 0.5])
        ADD2(w05, w, HALF2);        // (wx, wy) in [0, 1]
        unsigned xb, yb; upk_u(fm, xb, yb);
        float wxf, wyf;  upk_f(w05, wxf, wyf);
        unsigned m0 = yb & 15u;
        unsigned m1 = (yb + 1u) & 15u;
        unsigned off0 = yb * (SMS * 8u) + ((xb ^ m0) << 3) - KADJ;
        unsigned off1 = yb * (SMS * 8u) + ((xb ^ m1) << 3) - (KADJ - SMS * 8u);
        uint2 q0 = *(const uint2*)(tileb + off0);
        uint2 q1 = *(const uint2*)(tileb + off1);
        __half2 wx2 = __float2half2_rn(wxf);
        __half2 wy2 = __float2half2_rn(wyf);
        __half2 v00 = *(__half2*)&q0.x, v01 = *(__half2*)&q0.y;
        __half2 v10 = *(__half2*)&q1.x, v11 = *(__half2*)&q1.y;
        __half2 r0h = __hfma2(wx2, __hsub2(v01, v00), v00);
        __half2 r1h = __hfma2(wx2, __hsub2(v11, v10), v10);
        return __hfma2(wy2, __hsub2(r1h, r0h), r0h);
    };

    int aStart = (blk * NA) / NBLK;
    int aEnd   = ((blk + 1) * NA) / NBLK;
    float sc = scale[b];

    for (int ang0 = aStart; ang0 < aEnd; ang0 += CHUNK) {
        int na = aEnd - ang0; if (na > CHUNK) na = CHUNK;
        int items = na * ND;

        for (int it = tid; it < items; it += RBLK) {
            int al  = it / ND;
            int j   = it - al * ND;
            int ang = ang0 + al;
            float th  = (float)ang * 0.6020066889632107f;
            float rad = th * 0.017453292519943295f;
            float s, c;
            sincosf(rad, &s, &c);
            float u  = (float)j - 149.5f;
            float bx = fmaf(c,  u, fmaf(-149.5f, s, 73.5f));
            float by = fmaf(-s, u, fmaf(-149.5f, c, 73.5f));

            const float LO = 0.999f, HI = 146.001f;
            float t0 = 0.f, t1 = 299.f;
            bool empty = false;
            if (fabsf(s) > 1e-6f) {
                float ra = (LO - bx) / s, rb = (HI - bx) / s;
                t0 = fmaxf(t0, fminf(ra, rb));
                t1 = fminf(t1, fmaxf(ra, rb));
            } else if (bx <= LO || bx >= HI) empty = true;
            if (fabsf(c) > 1e-6f) {
                float ra = (LO - by) / c, rb = (HI - by) / c;
                t0 = fmaxf(t0, fminf(ra, rb));
                t1 = fminf(t1, fmaxf(ra, rb));
            } else if (by <= LO || by >= HI) empty = true;

            float S = 0.f, A = 0.f;
            if (!empty && t0 <= t1) {
                int i0 = (int)ceilf(t0);  if (i0 < 0)   i0 = 0;
                int i1 = (int)floorf(t1); if (i1 > 299) i1 = 299;
                int n  = i1 - i0 + 1;
                float bx5 = bx - 0.5f, by5 = by - 0.5f;
                unsigned long long pa = pk2(fmaf(s, (float)i0, bx5),
                                            fmaf(c, (float)i0, by5));
                unsigned long long st1 = pk2(s, c);
                unsigned long long st2 = pk2(s + s, c + c);
                unsigned long long pb;
                ADD2(pb, pa, st1);
                int k = 0;
#pragma unroll 1
                for (; k + 3 < n; k += 4) {
                    __half2 ra = samp(pa);
                    __half2 rb = samp(pb);
                    ADD2(pa, pa, st2);
                    ADD2(pb, pb, st2);
                    __half2 rc = samp(pa);
                    __half2 rd = samp(pb);
                    ADD2(pa, pa, st2);
                    ADD2(pb, pb, st2);
                    __half2 q  = __hadd2(__hadd2(ra, rb), __hadd2(rc, rd));
                    float2 f = __half22float2(q);
                    S += f.x; A += f.y;
                }
                if (k + 1 < n) {
                    __half2 ra = samp(pa);
                    __half2 rb = samp(pb);
                    __half2 q  = __hadd2(ra, rb);
                    float2 f = __half22float2(q);
                    S += f.x; A += f.y;
                    ADD2(pa, pa, st2);
                    k += 2;
                }
                if (k < n) {
                    float2 f = __half22float2(samp(pa));
                    S += f.x; A += f.y;
                }
            }
            srow[al * ND + j] = S * expf(-2.0f * A);
        }
        __syncthreads();

        float* o_base = out + (b * NA + ang0) * ND;
        for (int it = tid; it < items; it += RBLK) {
            int al  = it / ND;
            int j   = it - al * ND;
            int ang = ang0 + al;
            float th  = (float)ang * 0.6020066889632107f;
            float rad = th * 0.017453292519943295f;
            float s, c;
            sincosf(rad, &s, &c);
            float bw = 2.0f * (fabsf(c) + fabsf(s));
            float q  = 0.34657359027997264f * bw * bw;
            float e1 = expf(-q);
            float e2 = expf(-4.0f * q);
            float norm = 1.0f / (1.0f + 2.0f * e1 + 2.0f * e2);
            const float* row = srow + al * ND;
            int jm2 = j - 2; jm2 = jm2 < 0 ? -jm2 : jm2;
            int jm1 = j - 1; jm1 = jm1 < 0 ? -jm1 : jm1;
            int jp1 = j + 1; jp1 = jp1 > ND - 1 ? 2 * (ND - 1) - jp1 : jp1;
            int jp2 = j + 2; jp2 = jp2 > ND - 1 ? 2 * (ND - 1) - jp2 : jp2;
            float acc = row[j]
                      + e1 * (row[jm1] + row[jp1])
                      + e2 * (row[jm2] + row[jp2]);
            o_base[al * ND + j] = acc * norm * sc;
        }
        __syncthreads();
    }
}

// ---------------------------------------------------------------------------
extern "C" void kernel_launch(void* const* d_in, const int* in_sizes, int n_in,
                              void* d_out, int out_size) {
    const float* img   = (const float*)d_in[0];
    const float* att   = (const float*)d_in[1];
    const float* scale = (const float*)d_in[2];
    float* out = (float*)d_out;
    (void)in_sizes; (void)n_in; (void)out_size;

    cudaFuncSetAttribute(prep_kernel,  cudaFuncAttributeMaxDynamicSharedMemorySize,
                         128 * CPB * (int)sizeof(float2));
    cudaFuncSetAttribute(radon_kernel, cudaFuncAttributeMaxDynamicSharedMemorySize,
                         RAD_SMEM);

    prep_kernel<<<dim3(4, NB), 512, 128 * CPB * sizeof(float2)>>>(img, att);
    radon_kernel<<<dim3(NBLK, NB), RBLK, RAD_SMEM>>>(scale, out);
}

// round 7
// speedup vs baseline: 2.1217x; 1.0559x over previous
#include <cuda_runtime.h>
#include <cuda_fp16.h>
#include <math.h>

// ---------------------------------------------------------------------------
// PET forward, round 7:
//  - prep (64 blocks, column-split): H+V Gaussian blur -> fp16 x-dup records
//  - radon: one-wave grid (9 x 16), tile staged once. Per-angle parameter
//    table in smem (s, c, 1/s, 1/c, e1, e2, norm) kills per-item sincos/div/
//    exp. FOUR independent packed-f32x2 walkers per thread for ILP. Weight
//    broadcast via one F2FP + half-lane selectors. Quad fp16 accumulation,
//    fused attenuation + detector-blur + scale epilogue.
// ---------------------------------------------------------------------------

#define NB 16
#define NA 300
#define ND 300
#define TS 148
#define SMS 160
#define NBLK 9
#define CHUNK 12
#define RBLK 1024
#define CPB 37
#define MAXANG 34     // max angles per block (ceil(300/9)+1)

#define TILE_BYTES (TS * SMS * 8)                       // 189440
#define SROW_BYTES (CHUNK * ND * 4)                     // 14400
#define RAD_SMEM   (TILE_BYTES + SROW_BYTES + MAXANG * 32)

__device__ uint2 g_tile[NB][TS][TS];

// ---- packed f32x2 helpers --------------------------------------------------
#define ADD2(d,a,b)   asm("add.rn.f32x2 %0, %1, %2;" : "=l"(d) : "l"(a), "l"(b))
#define FMA2(d,a,b,c) asm("fma.rn.f32x2 %0, %1, %2, %3;" : "=l"(d) : "l"(a), "l"(b), "l"(c))

__device__ __forceinline__ unsigned long long pk2(float a, float b) {
    unsigned long long r;
    asm("mov.b64 %0, {%1, %2};" : "=l"(r) : "f"(a), "f"(b));
    return r;
}
__device__ __forceinline__ void upk_u(unsigned long long a, unsigned& lo, unsigned& hi) {
    asm("mov.b64 {%0, %1}, %2;" : "=r"(lo), "=r"(hi) : "l"(a));
}
__device__ __forceinline__ void upk_f(unsigned long long a, float& lo, float& hi) {
    asm("mov.b64 {%0, %1}, %2;" : "=f"(lo), "=f"(hi) : "l"(a));
}

// ---------------------------------------------------------------------------
__global__ __launch_bounds__(512, 2) void prep_kernel(
        const float* __restrict__ img, const float* __restrict__ att) {
    extern __shared__ float2 Hs[];          // [128][CPB]
    __shared__ float K4[9], K8[17];
    int b  = blockIdx.y;
    int c0 = blockIdx.x * CPB;
    int tid = threadIdx.x;

    if (tid == 0) {
        const float sig_i = 1.2011224087864498f;
        const float sig_a = 2.4022448175728997f;
        float w4[9], s4 = 0.f, w8[17], s8 = 0.f;
        for (int d = -4; d <= 4; ++d) { float w = expf(-0.5f*(d/sig_i)*(d/sig_i)); w4[d+4] = w; s4 += w; }
        for (int i = 0; i < 9; ++i) K4[i] = w4[i] / s4;
        for (int d = -8; d <= 8; ++d) { float w = expf(-0.5f*(d/sig_a)*(d/sig_a)); w8[d+8] = w; s8 += w; }
        for (int i = 0; i < 17; ++i) K8[i] = w8[i] / s8;
    }
    __syncthreads();

    const float* ib = img + b * 128 * 128;
    const float* ab = att + b * 128 * 128;
    for (int idx = tid; idx < 128 * CPB; idx += blockDim.x) {
        int cl = idx % CPB, y = idx / CPB;
        int xc = c0 + cl - 10;
        float a0 = 0.f, a1 = 0.f;
        const float* ir = ib + y * 128;
        const float* ar = ab + y * 128;
#pragma unroll
        for (int d = -8; d <= 8; ++d) {
            int xi = xc + d;
            if (xi >= 0 && xi < 128) {
                a1 += K8[d + 8] * ar[xi];
                if (d >= -4 && d <= 4) a0 += K4[d + 4] * ir[xi];
            }
        }
        Hs[idx] = make_float2(a0, a1);
    }
    __syncthreads();

    unsigned* gt = (unsigned*)&g_tile[b][0][0];
    for (int idx = tid; idx < TS * CPB; idx += blockDim.x) {
        int cl = idx % CPB, r = idx / CPB;
        int c  = c0 + cl;
        int yc = r - 10;
        float a0 = 0.f, a1 = 0.f;
#pragma unroll
        for (int d = -8; d <= 8; ++d) {
            int yi = yc + d;
            if (yi >= 0 && yi < 128) {
                float2 t = Hs[yi * CPB + cl];
                a1 += K8[d + 8] * t.y;
                if (d >= -4 && d <= 4) a0 += K4[d + 4] * t.x;
            }
        }
        __half2 h = __floats2half2_rn(a0, a1 * 0.01f);
        unsigned u = *(unsigned*)&h;
        gt[(r * TS + c) * 2 + 0] = u;
        if (c > 0)       gt[(r * TS + c - 1) * 2 + 1] = u;
        if (c == TS - 1) gt[(r * TS + c) * 2 + 1] = 0;
    }
}

// ---------------------------------------------------------------------------
#define MAGF 8388608.0f   // 2^23
#define KADJ (0x4B000000u * (unsigned)(SMS * 8) + 0x4B000000u * 8u)

__global__ __launch_bounds__(RBLK, 1) void radon_kernel(
        const float* __restrict__ scale, float* __restrict__ out) {
    extern __shared__ char dyn[];
    char*   tileb = dyn;
    float*  srow  = (float*)(dyn + TILE_BYTES);                 // [CHUNK][ND]
    float4* tab0  = (float4*)(dyn + TILE_BYTES + SROW_BYTES);   // s,c,1/s,1/c
    float4* tab1  = tab0 + MAXANG;                              // e1,e2,norm

    int b   = blockIdx.y;
    int blk = blockIdx.x;
    int tid = threadIdx.x;

    int aStart = (blk * NA) / NBLK;
    int aEnd   = ((blk + 1) * NA) / NBLK;
    int nAng   = aEnd - aStart;

    // Per-angle parameter table (once per block)
    for (int a = tid; a < nAng; a += RBLK) {
        int ang = aStart + a;
        float th  = (float)ang * 0.6020066889632107f;     // *180/299
        float rad = th * 0.017453292519943295f;
        float s, c;
        sincosf(rad, &s, &c);
        tab0[a] = make_float4(s, c, 1.0f / s, 1.0f / c);
        float bw = 2.0f * (fabsf(c) + fabsf(s));
        float q  = 0.34657359027997264f * bw * bw;        // 0.5*ln2*bw^2
        float e1 = __expf(-q);
        float e2 = __expf(-4.0f * q);
        float norm = 1.0f / (1.0f + 2.0f * e1 + 2.0f * e2);
        tab1[a] = make_float4(e1, e2, norm, 0.f);
    }

    // Stage tile once (XOR swizzle on record column)
    {
        uint2* tile = (uint2*)tileb;
        const uint2* gt = &g_tile[b][0][0];
        for (int i = tid; i < TS * TS; i += RBLK) {
            int y = i / TS, x = i - y * TS;
            tile[y * SMS + (x ^ (y & 15))] = gt[i];
        }
    }
    __syncthreads();

    const unsigned long long MAG2  = pk2(MAGF, MAGF);
    const unsigned long long NMAG2 = pk2(-MAGF, -MAGF);
    const unsigned long long NEG12 = pk2(-1.0f, -1.0f);
    const unsigned long long HALF2 = pk2(0.5f, 0.5f);

    // p carries (lx-0.5, ly-0.5); magic-rn floor (exact-integer tie -> w==1.0,
    // bilinear still exact).
    auto samp = [&](unsigned long long p) -> __half2 {
        unsigned long long fm, t, w, w05;
        ADD2(fm, p, MAG2);
        ADD2(t,  fm, NMAG2);
        FMA2(w,  t, NEG12, p);       // p - t, exact in [-0.5, 0.5]
        ADD2(w05, w, HALF2);
        unsigned xb, yb; upk_u(fm, xb, yb);
        float wxf, wyf;  upk_f(w05, wxf, wyf);
        unsigned m0 = yb & 15u;
        unsigned m1 = (yb + 1u) & 15u;
        unsigned base = yb * (SMS * 8u);
        unsigned off0 = base + ((xb ^ m0) << 3) - KADJ;
        unsigned off1 = base + ((xb ^ m1) << 3) - (KADJ - SMS * 8u);
        uint2 q0 = *(const uint2*)(tileb + off0);
        uint2 q1 = *(const uint2*)(tileb + off1);
        __half2 wpk = __floats2half2_rn(wxf, wyf);  // one F2FP
        __half2 wx2 = __low2half2(wpk);             // folds to .H0_H0 selector
        __half2 wy2 = __high2half2(wpk);            // folds to .H1_H1 selector
        __half2 v00 = *(__half2*)&q0.x, v01 = *(__half2*)&q0.y;
        __half2 v10 = *(__half2*)&q1.x, v11 = *(__half2*)&q1.y;
        __half2 r0h = __hfma2(wx2, __hsub2(v01, v00), v00);
        __half2 r1h = __hfma2(wx2, __hsub2(v11, v10), v10);
        return __hfma2(wy2, __hsub2(r1h, r0h), r0h);
    };

    float sc = scale[b];

    for (int ang0 = aStart; ang0 < aEnd; ang0 += CHUNK) {
        int na = aEnd - ang0; if (na > CHUNK) na = CHUNK;
        int items = na * ND;
        int tabBase = ang0 - aStart;

        for (int it = tid; it < items; it += RBLK) {
            int al = it / ND;
            int j  = it - al * ND;
            float4 T = tab0[tabBase + al];
            float s = T.x, c = T.y, is = T.z, ic = T.w;
            float u  = (float)j - 149.5f;
            float bx = fmaf(c,  u, fmaf(-149.5f, s, 73.5f));
            float by = fmaf(-s, u, fmaf(-149.5f, c, 73.5f));

            const float LO = 0.999f, HI = 146.001f;
            float rxa = (LO - bx) * is, rxb = (HI - bx) * is;
            float rya = (LO - by) * ic, ryb = (HI - by) * ic;
            float t0 = fmaxf(0.f,   fmaxf(fminf(rxa, rxb), fminf(rya, ryb)));
            float t1 = fminf(299.f, fminf(fmaxf(rxa, rxb), fmaxf(rya, ryb)));

            float S = 0.f, A = 0.f;
            if (t0 <= t1) {
                int i0 = (int)ceilf(t0);
                int i1 = (int)floorf(t1);
                int n  = i1 - i0 + 1;
                float bx5 = bx - 0.5f, by5 = by - 0.5f;
                float lx0 = fmaf(s, (float)i0, bx5);
                float ly0 = fmaf(c, (float)i0, by5);
                unsigned long long st1 = pk2(s, c);
                unsigned long long st4 = pk2(4.f * s, 4.f * c);
                unsigned long long p0 = pk2(lx0, ly0);
                unsigned long long p1, p2, p3;
                ADD2(p1, p0, st1);
                ADD2(p2, p1, st1);
                ADD2(p3, p2, st1);
                int k = 0;
#pragma unroll 1
                for (; k + 3 < n; k += 4) {
                    __half2 ra = samp(p0);
                    __half2 rb = samp(p1);
                    __half2 rc = samp(p2);
                    __half2 rd = samp(p3);
                    ADD2(p0, p0, st4);
                    ADD2(p1, p1, st4);
                    ADD2(p2, p2, st4);
                    ADD2(p3, p3, st4);
                    __half2 q = __hadd2(__hadd2(ra, rb), __hadd2(rc, rd));
                    float2 f = __half22float2(q);
                    S += f.x; A += f.y;
                }
#pragma unroll 1
                for (; k < n; ++k) {
                    float2 f = __half22float2(samp(p0));
                    S += f.x; A += f.y;
                    ADD2(p0, p0, st1);
                }
            }
            srow[al * ND + j] = S * __expf(-2.0f * A);
        }
        __syncthreads();

        float* o_base = out + (b * NA + ang0) * ND;
        for (int it = tid; it < items; it += RBLK) {
            int al = it / ND;
            int j  = it - al * ND;
            float4 E = tab1[tabBase + al];
            float e1 = E.x, e2 = E.y, norm = E.z;
            const float* row = srow + al * ND;
            int jm2 = j - 2; jm2 = jm2 < 0 ? -jm2 : jm2;
            int jm1 = j - 1; jm1 = jm1 < 0 ? -jm1 : jm1;
            int jp1 = j + 1; jp1 = jp1 > ND - 1 ? 2 * (ND - 1) - jp1 : jp1;
            int jp2 = j + 2; jp2 = jp2 > ND - 1 ? 2 * (ND - 1) - jp2 : jp2;
            float acc = row[j]
                      + e1 * (row[jm1] + row[jp1])
                      + e2 * (row[jm2] + row[jp2]);
            o_base[al * ND + j] = acc * norm * sc;
        }
        __syncthreads();
    }
}

// ---------------------------------------------------------------------------
extern "C" void kernel_launch(void* const* d_in, const int* in_sizes, int n_in,
                              void* d_out, int out_size) {
    const float* img   = (const float*)d_in[0];
    const float* att   = (const float*)d_in[1];
    const float* scale = (const float*)d_in[2];
    float* out = (float*)d_out;
    (void)in_sizes; (void)n_in; (void)out_size;

    cudaFuncSetAttribute(prep_kernel,  cudaFuncAttributeMaxDynamicSharedMemorySize,
                         128 * CPB * (int)sizeof(float2));
    cudaFuncSetAttribute(radon_kernel, cudaFuncAttributeMaxDynamicSharedMemorySize,
                         RAD_SMEM);

    prep_kernel<<<dim3(4, NB), 512, 128 * CPB * sizeof(float2)>>>(img, att);
    radon_kernel<<<dim3(NBLK, NB), RBLK, RAD_SMEM>>>(scale, out);
}

// round 8
// speedup vs baseline: 2.3151x; 1.0912x over previous
#include <cuda_runtime.h>
#include <cuda_fp16.h>
#include <math.h>

// ---------------------------------------------------------------------------
// PET forward, round 8:
//  - prep (128 blocks, column-split with halo): H+V blur staged in smem,
//    tile stored as (m,d) fp16 records: slot0 = half2(m_e, m_a),
//    slot1 = half2(d_e, d_a), m = (v(x)+v(x+1))/2, d = v(x+1)-v(x).
//  - radon: one-wave grid (9 x 16), tile staged once, per-angle param table.
//    Bilinear row lerp = ONE HFMA2 (centered weight on (m,d) records).
//    Floor+weights in 3 packed f32x2 ops via asymmetric magic (2^23, 2^23-0.5).
//    4 independent walkers, quad fp16 accumulation, fused epilogue.
// ---------------------------------------------------------------------------

#define NB 16
#define NA 300
#define ND 300
#define TS 148
#define SMS 160
#define NBLK 9
#define CHUNK 12
#define RBLK 1024
#define NSPLIT 8
#define CPB 19        // ceil(148/8)
#define MAXANG 34

#define TILE_BYTES (TS * SMS * 8)
#define SROW_BYTES (CHUNK * ND * 4)
#define RAD_SMEM   (TILE_BYTES + SROW_BYTES + MAXANG * 32)

__device__ uint2 g_tile[NB][TS][TS];

// ---- packed f32x2 helpers --------------------------------------------------
#define ADD2(d,a,b)   asm("add.rn.f32x2 %0, %1, %2;" : "=l"(d) : "l"(a), "l"(b))
#define FMA2(d,a,b,c) asm("fma.rn.f32x2 %0, %1, %2, %3;" : "=l"(d) : "l"(a), "l"(b), "l"(c))

__device__ __forceinline__ unsigned long long pk2(float a, float b) {
    unsigned long long r;
    asm("mov.b64 %0, {%1, %2};" : "=l"(r) : "f"(a), "f"(b));
    return r;
}
__device__ __forceinline__ void upk_u(unsigned long long a, unsigned& lo, unsigned& hi) {
    asm("mov.b64 {%0, %1}, %2;" : "=r"(lo), "=r"(hi) : "l"(a));
}
__device__ __forceinline__ void upk_f(unsigned long long a, float& lo, float& hi) {
    asm("mov.b64 {%0, %1}, %2;" : "=f"(lo), "=f"(hi) : "l"(a));
}

// ---------------------------------------------------------------------------
// prep: grid (NSPLIT, NB). Block owns cols [c0, c0+CPB); computes V-pass for
// [c0, c0+CPB] (one halo col) in smem, then writes (m,d) records.
__global__ __launch_bounds__(512, 2) void prep_kernel(
        const float* __restrict__ img, const float* __restrict__ att) {
    extern __shared__ float2 dynp[];
    float2* Hs = dynp;                    // [128][CPB+1]
    float2* Vs = dynp + 128 * (CPB + 1);  // [TS][CPB+1]
    __shared__ float K4[9], K8[17];
    int b  = blockIdx.y;
    int c0 = blockIdx.x * CPB;
    int tid = threadIdx.x;
    int ncol = CPB + 1;                   // halo column (may exceed TS; value 0)

    if (tid == 0) {
        const float sig_i = 1.2011224087864498f;
        const float sig_a = 2.4022448175728997f;
        float w4[9], s4 = 0.f, w8[17], s8 = 0.f;
        for (int d = -4; d <= 4; ++d) { float w = expf(-0.5f*(d/sig_i)*(d/sig_i)); w4[d+4] = w; s4 += w; }
        for (int i = 0; i < 9; ++i) K4[i] = w4[i] / s4;
        for (int d = -8; d <= 8; ++d) { float w = expf(-0.5f*(d/sig_a)*(d/sig_a)); w8[d+8] = w; s8 += w; }
        for (int i = 0; i < 17; ++i) K8[i] = w8[i] / s8;
    }
    __syncthreads();

    const float* ib = img + b * 128 * 128;
    const float* ab = att + b * 128 * 128;
    for (int idx = tid; idx < 128 * ncol; idx += blockDim.x) {
        int cl = idx % ncol, y = idx / ncol;
        int xc = c0 + cl - 10;
        float a0 = 0.f, a1 = 0.f;
        const float* ir = ib + y * 128;
        const float* ar = ab + y * 128;
#pragma unroll
        for (int d = -8; d <= 8; ++d) {
            int xi = xc + d;
            if (xi >= 0 && xi < 128) {
                a1 += K8[d + 8] * ar[xi];
                if (d >= -4 && d <= 4) a0 += K4[d + 4] * ir[xi];
            }
        }
        Hs[idx] = make_float2(a0, a1);
    }
    __syncthreads();

    for (int idx = tid; idx < TS * ncol; idx += blockDim.x) {
        int cl = idx % ncol, r = idx / ncol;
        int yc = r - 10;
        float a0 = 0.f, a1 = 0.f;
#pragma unroll
        for (int d = -8; d <= 8; ++d) {
            int yi = yc + d;
            if (yi >= 0 && yi < 128) {
                float2 t = Hs[yi * ncol + cl];
                a1 += K8[d + 8] * t.y;
                if (d >= -4 && d <= 4) a0 += K4[d + 4] * t.x;
            }
        }
        Vs[idx] = make_float2(a0, a1 * 0.01f);
    }
    __syncthreads();

    // (m,d) records for columns [c0, min(c0+CPB, TS))
    uint2* gt = (uint2*)&g_tile[b][0][0];
    for (int idx = tid; idx < TS * CPB; idx += blockDim.x) {
        int cl = idx % CPB, r = idx / CPB;
        int c  = c0 + cl;
        if (c >= TS) continue;
        float2 v0 = Vs[r * ncol + cl];
        float2 v1 = Vs[r * ncol + cl + 1];
        __half2 m = __floats2half2_rn(0.5f * (v0.x + v1.x), 0.5f * (v0.y + v1.y));
        __half2 d = __floats2half2_rn(v1.x - v0.x, v1.y - v0.y);
        uint2 rec;
        rec.x = *(unsigned*)&m;
        rec.y = *(unsigned*)&d;
        gt[r * TS + c] = rec;
    }
}

// ---------------------------------------------------------------------------
#define MAGF 8388608.0f    // 2^23
#define MAGY 8388607.5f    // 2^23 - 0.5 (exactly representable)
#define KADJ (0x4B000000u * (unsigned)(SMS * 8) + 0x4B000000u * 8u)

__global__ __launch_bounds__(RBLK, 1) void radon_kernel(
        const float* __restrict__ scale, float* __restrict__ out) {
    extern __shared__ char dyn[];
    char*   tileb = dyn;
    float*  srow  = (float*)(dyn + TILE_BYTES);                 // [CHUNK][ND]
    float4* tab0  = (float4*)(dyn + TILE_BYTES + SROW_BYTES);   // s,c,1/s,1/c
    float4* tab1  = tab0 + MAXANG;                              // e1,e2,norm

    int b   = blockIdx.y;
    int blk = blockIdx.x;
    int tid = threadIdx.x;

    int aStart = (blk * NA) / NBLK;
    int aEnd   = ((blk + 1) * NA) / NBLK;
    int nAng   = aEnd - aStart;

    for (int a = tid; a < nAng; a += RBLK) {
        int ang = aStart + a;
        float th  = (float)ang * 0.6020066889632107f;     // *180/299
        float rad = th * 0.017453292519943295f;
        float s, c;
        sincosf(rad, &s, &c);
        tab0[a] = make_float4(s, c, 1.0f / s, 1.0f / c);
        float bw = 2.0f * (fabsf(c) + fabsf(s));
        float q  = 0.34657359027997264f * bw * bw;        // 0.5*ln2*bw^2
        float e1 = __expf(-q);
        float e2 = __expf(-4.0f * q);
        float norm = 1.0f / (1.0f + 2.0f * e1 + 2.0f * e2);
        tab1[a] = make_float4(e1, e2, norm, 0.f);
    }

    {
        uint2* tile = (uint2*)tileb;
        const uint2* gt = &g_tile[b][0][0];
        for (int i = tid; i < TS * TS; i += RBLK) {
            int y = i / TS, x = i - y * TS;
            tile[y * SMS + (x ^ (y & 15))] = gt[i];
        }
    }
    __syncthreads();

    const unsigned long long MAG2  = pk2(MAGF, MAGY);     // asymmetric magic
    const unsigned long long NMAG2 = pk2(-MAGF, -MAGF);
    const unsigned long long NEG12 = pk2(-1.0f, -1.0f);

    // Walker q = (lx-0.5, ly).
    //   fm = q + (2^23, 2^23-0.5)  -> (bias+floor(lx), bias+floor(ly))   [rn ties
    //        land on weight exactly 0/1 -> bilinear exact]
    //   t  = fm - 2^23             -> exact (rx, ry)
    //   w  = q - t                 -> (wx_c in [-.5,.5], wy in [0,1])
    auto samp = [&](unsigned long long q) -> __half2 {
        unsigned long long fm, t, w;
        ADD2(fm, q, MAG2);
        ADD2(t,  fm, NMAG2);
        FMA2(w,  t, NEG12, q);
        unsigned xb, yb; upk_u(fm, xb, yb);
        float wxf, wyf;  upk_f(w, xb ? wxf : wxf, wyf);   // (no-op select, just unpack)
        unsigned m0 = yb & 15u;
        unsigned m1 = (yb + 1u) & 15u;
        unsigned base = yb * (SMS * 8u);
        unsigned off0 = base + ((xb ^ m0) << 3) - KADJ;
        unsigned off1 = base + ((xb ^ m1) << 3) - (KADJ - SMS * 8u);
        uint2 q0 = *(const uint2*)(tileb + off0);
        uint2 q1 = *(const uint2*)(tileb + off1);
        __half2 wpk = __floats2half2_rn(wxf, wyf);  // one F2FP
        __half2 wx2 = __low2half2(wpk);             // .H0_H0 selector
        __half2 wy2 = __high2half2(wpk);            // .H1_H1 selector
        __half2 m0h = *(__half2*)&q0.x, d0h = *(__half2*)&q0.y;
        __half2 m1h = *(__half2*)&q1.x, d1h = *(__half2*)&q1.y;
        __half2 r0h = __hfma2(wx2, d0h, m0h);       // row lerp: ONE fma
        __half2 r1h = __hfma2(wx2, d1h, m1h);
        __half2 hs  = __hsub2(r1h, r0h);
        return __hfma2(wy2, hs, r0h);
    };

    float sc = scale[b];

    for (int ang0 = aStart; ang0 < aEnd; ang0 += CHUNK) {
        int na = aEnd - ang0; if (na > CHUNK) na = CHUNK;
        int items = na * ND;
        int tabBase = ang0 - aStart;

        for (int it = tid; it < items; it += RBLK) {
            int al = it / ND;
            int j  = it - al * ND;
            float4 T = tab0[tabBase + al];
            float s = T.x, c = T.y, is = T.z, ic = T.w;
            float u  = (float)j - 149.5f;
            float bx = fmaf(c,  u, fmaf(-149.5f, s, 73.5f));
            float by = fmaf(-s, u, fmaf(-149.5f, c, 73.5f));

            const float LO = 0.999f, HI = 146.001f;
            float rxa = (LO - bx) * is, rxb = (HI - bx) * is;
            float rya = (LO - by) * ic, ryb = (HI - by) * ic;
            float t0 = fmaxf(0.f,   fmaxf(fminf(rxa, rxb), fminf(rya, ryb)));
            float t1 = fminf(299.f, fminf(fmaxf(rxa, rxb), fmaxf(rya, ryb)));

            float S = 0.f, A = 0.f;
            if (t0 <= t1) {
                int i0 = (int)ceilf(t0);
                int i1 = (int)floorf(t1);
                int n  = i1 - i0 + 1;
                float lx0 = fmaf(s, (float)i0, bx - 0.5f);
                float ly0 = fmaf(c, (float)i0, by);
                unsigned long long st1 = pk2(s, c);
                unsigned long long st4 = pk2(4.f * s, 4.f * c);
                unsigned long long p0 = pk2(lx0, ly0);
                unsigned long long p1, p2, p3;
                ADD2(p1, p0, st1);
                ADD2(p2, p1, st1);
                ADD2(p3, p2, st1);
                int k = 0;
#pragma unroll 1
                for (; k + 3 < n; k += 4) {
                    __half2 ra = samp(p0);
                    __half2 rb = samp(p1);
                    __half2 rc = samp(p2);
                    __half2 rd = samp(p3);
                    ADD2(p0, p0, st4);
                    ADD2(p1, p1, st4);
                    ADD2(p2, p2, st4);
                    ADD2(p3, p3, st4);
                    __half2 qq = __hadd2(__hadd2(ra, rb), __hadd2(rc, rd));
                    float2 f = __half22float2(qq);
                    S += f.x; A += f.y;
                }
#pragma unroll 1
                for (; k < n; ++k) {
                    float2 f = __half22float2(samp(p0));
                    S += f.x; A += f.y;
                    ADD2(p0, p0, st1);
                }
            }
            srow[al * ND + j] = S * __expf(-2.0f * A);
        }
        __syncthreads();

        float* o_base = out + (b * NA + ang0) * ND;
        for (int it = tid; it < items; it += RBLK) {
            int al = it / ND;
            int j  = it - al * ND;
            float4 E = tab1[tabBase + al];
            float e1 = E.x, e2 = E.y, norm = E.z;
            const float* row = srow + al * ND;
            int jm2 = j - 2; jm2 = jm2 < 0 ? -jm2 : jm2;
            int jm1 = j - 1; jm1 = jm1 < 0 ? -jm1 : jm1;
            int jp1 = j + 1; jp1 = jp1 > ND - 1 ? 2 * (ND - 1) - jp1 : jp1;
            int jp2 = j + 2; jp2 = jp2 > ND - 1 ? 2 * (ND - 1) - jp2 : jp2;
            float acc = row[j]
                      + e1 * (row[jm1] + row[jp1])
                      + e2 * (row[jm2] + row[jp2]);
            o_base[al * ND + j] = acc * norm * sc;
        }
        __syncthreads();
    }
}

// ---------------------------------------------------------------------------
extern "C" void kernel_launch(void* const* d_in, const int* in_sizes, int n_in,
                              void* d_out, int out_size) {
    const float* img   = (const float*)d_in[0];
    const float* att   = (const float*)d_in[1];
    const float* scale = (const float*)d_in[2];
    float* out = (float*)d_out;
    (void)in_sizes; (void)n_in; (void)out_size;

    int prep_smem = (128 + TS) * (CPB + 1) * (int)sizeof(float2);
    cudaFuncSetAttribute(prep_kernel,  cudaFuncAttributeMaxDynamicSharedMemorySize,
                         prep_smem);
    cudaFuncSetAttribute(radon_kernel, cudaFuncAttributeMaxDynamicSharedMemorySize,
                         RAD_SMEM);

    prep_kernel<<<dim3(NSPLIT, NB), 512, prep_smem>>>(img, att);
    radon_kernel<<<dim3(NBLK, NB), RBLK, RAD_SMEM>>>(scale, out);
}

// round 9
// speedup vs baseline: 2.3807x; 1.0283x over previous
#include <cuda_runtime.h>
#include <cuda_fp16.h>
#include <math.h>

// ---------------------------------------------------------------------------
// PET forward, round 9:
//  - prep (128 blocks, column-split with halo): H+V blur, (m,d) fp16 records.
//  - radon: one-wave grid (9 x 16), tile staged once, per-angle param table.
//    Software-pipelined inner loop: 8 LDS.64 issued back-to-back for 4
//    independent packed-f32x2 walkers, then interpolation math (HFMA2 on
//    (m,d) records, centered weights). CHUNK=17 (2 chunks/block). Quad fp16
//    accumulation, fused attenuation + detector-blur + scale epilogue.
// ---------------------------------------------------------------------------

#define NB 16
#define NA 300
#define ND 300
#define TS 148
#define SMS 160
#define NBLK 9
#define CHUNK 17
#define RBLK 1024
#define NSPLIT 8
#define CPB 19
#define MAXANG 34

#define TILE_BYTES (TS * SMS * 8)
#define SROW_BYTES (CHUNK * ND * 4)
#define RAD_SMEM   (TILE_BYTES + SROW_BYTES + MAXANG * 32)

__device__ uint2 g_tile[NB][TS][TS];

// ---- packed f32x2 helpers --------------------------------------------------
#define ADD2(d,a,b)   asm("add.rn.f32x2 %0, %1, %2;" : "=l"(d) : "l"(a), "l"(b))
#define FMA2(d,a,b,c) asm("fma.rn.f32x2 %0, %1, %2, %3;" : "=l"(d) : "l"(a), "l"(b), "l"(c))

__device__ __forceinline__ unsigned long long pk2(float a, float b) {
    unsigned long long r;
    asm("mov.b64 %0, {%1, %2};" : "=l"(r) : "f"(a), "f"(b));
    return r;
}
__device__ __forceinline__ void upk_u(unsigned long long a, unsigned& lo, unsigned& hi) {
    asm("mov.b64 {%0, %1}, %2;" : "=r"(lo), "=r"(hi) : "l"(a));
}
__device__ __forceinline__ void upk_f(unsigned long long a, float& lo, float& hi) {
    asm("mov.b64 {%0, %1}, %2;" : "=f"(lo), "=f"(hi) : "l"(a));
}

// ---------------------------------------------------------------------------
__global__ __launch_bounds__(512, 2) void prep_kernel(
        const float* __restrict__ img, const float* __restrict__ att) {
    extern __shared__ float2 dynp[];
    float2* Hs = dynp;                    // [128][CPB+1]
    float2* Vs = dynp + 128 * (CPB + 1);  // [TS][CPB+1]
    __shared__ float K4[9], K8[17];
    int b  = blockIdx.y;
    int c0 = blockIdx.x * CPB;
    int tid = threadIdx.x;
    int ncol = CPB + 1;

    if (tid == 0) {
        const float sig_i = 1.2011224087864498f;
        const float sig_a = 2.4022448175728997f;
        float w4[9], s4 = 0.f, w8[17], s8 = 0.f;
        for (int d = -4; d <= 4; ++d) { float w = expf(-0.5f*(d/sig_i)*(d/sig_i)); w4[d+4] = w; s4 += w; }
        for (int i = 0; i < 9; ++i) K4[i] = w4[i] / s4;
        for (int d = -8; d <= 8; ++d) { float w = expf(-0.5f*(d/sig_a)*(d/sig_a)); w8[d+8] = w; s8 += w; }
        for (int i = 0; i < 17; ++i) K8[i] = w8[i] / s8;
    }
    __syncthreads();

    const float* ib = img + b * 128 * 128;
    const float* ab = att + b * 128 * 128;
    for (int idx = tid; idx < 128 * ncol; idx += blockDim.x) {
        int cl = idx % ncol, y = idx / ncol;
        int xc = c0 + cl - 10;
        float a0 = 0.f, a1 = 0.f;
        const float* ir = ib + y * 128;
        const float* ar = ab + y * 128;
#pragma unroll
        for (int d = -8; d <= 8; ++d) {
            int xi = xc + d;
            if (xi >= 0 && xi < 128) {
                a1 += K8[d + 8] * ar[xi];
                if (d >= -4 && d <= 4) a0 += K4[d + 4] * ir[xi];
            }
        }
        Hs[idx] = make_float2(a0, a1);
    }
    __syncthreads();

    for (int idx = tid; idx < TS * ncol; idx += blockDim.x) {
        int cl = idx % ncol, r = idx / ncol;
        int yc = r - 10;
        float a0 = 0.f, a1 = 0.f;
#pragma unroll
        for (int d = -8; d <= 8; ++d) {
            int yi = yc + d;
            if (yi >= 0 && yi < 128) {
                float2 t = Hs[yi * ncol + cl];
                a1 += K8[d + 8] * t.y;
                if (d >= -4 && d <= 4) a0 += K4[d + 4] * t.x;
            }
        }
        Vs[idx] = make_float2(a0, a1 * 0.01f);
    }
    __syncthreads();

    uint2* gt = (uint2*)&g_tile[b][0][0];
    for (int idx = tid; idx < TS * CPB; idx += blockDim.x) {
        int cl = idx % CPB, r = idx / CPB;
        int c  = c0 + cl;
        if (c >= TS) continue;
        float2 v0 = Vs[r * ncol + cl];
        float2 v1 = Vs[r * ncol + cl + 1];
        __half2 m = __floats2half2_rn(0.5f * (v0.x + v1.x), 0.5f * (v0.y + v1.y));
        __half2 d = __floats2half2_rn(v1.x - v0.x, v1.y - v0.y);
        uint2 rec;
        rec.x = *(unsigned*)&m;
        rec.y = *(unsigned*)&d;
        gt[r * TS + c] = rec;
    }
}

// ---------------------------------------------------------------------------
#define MAGF 8388608.0f    // 2^23
#define MAGY 8388607.5f    // 2^23 - 0.5
#define KADJ (0x4B000000u * (unsigned)(SMS * 8) + 0x4B000000u * 8u)

__global__ __launch_bounds__(RBLK, 1) void radon_kernel(
        const float* __restrict__ scale, float* __restrict__ out) {
    extern __shared__ char dyn[];
    char*   tileb = dyn;
    float*  srow  = (float*)(dyn + TILE_BYTES);                 // [CHUNK][ND]
    float4* tab0  = (float4*)(dyn + TILE_BYTES + SROW_BYTES);   // s,c,1/s,1/c
    float4* tab1  = tab0 + MAXANG;                              // e1,e2,norm

    int b   = blockIdx.y;
    int blk = blockIdx.x;
    int tid = threadIdx.x;

    int aStart = (blk * NA) / NBLK;
    int aEnd   = ((blk + 1) * NA) / NBLK;
    int nAng   = aEnd - aStart;

    for (int a = tid; a < nAng; a += RBLK) {
        int ang = aStart + a;
        float th  = (float)ang * 0.6020066889632107f;
        float rad = th * 0.017453292519943295f;
        float s, c;
        sincosf(rad, &s, &c);
        tab0[a] = make_float4(s, c, 1.0f / s, 1.0f / c);
        float bw = 2.0f * (fabsf(c) + fabsf(s));
        float q  = 0.34657359027997264f * bw * bw;
        float e1 = __expf(-q);
        float e2 = __expf(-4.0f * q);
        float norm = 1.0f / (1.0f + 2.0f * e1 + 2.0f * e2);
        tab1[a] = make_float4(e1, e2, norm, 0.f);
    }

    {
        uint2* tile = (uint2*)tileb;
        const uint2* gt = &g_tile[b][0][0];
        for (int i = tid; i < TS * TS; i += RBLK) {
            int y = i / TS, x = i - y * TS;
            tile[y * SMS + (x ^ (y & 15))] = gt[i];
        }
    }
    __syncthreads();

    const unsigned long long MAG2  = pk2(MAGF, MAGY);
    const unsigned long long NMAG2 = pk2(-MAGF, -MAGF);
    const unsigned long long NEG12 = pk2(-1.0f, -1.0f);

    // Phase 1: magic-add + address + both LDS.64 (issue loads early).
    auto fetch = [&](unsigned long long q, unsigned long long& fm,
                     uint2& q0, uint2& q1) {
        ADD2(fm, q, MAG2);
        unsigned xb, yb; upk_u(fm, xb, yb);
        unsigned m0 = yb & 15u;
        unsigned m1 = (yb + 1u) & 15u;
        unsigned base = yb * (SMS * 8u);
        unsigned off0 = base + ((xb ^ m0) << 3) - KADJ;
        unsigned off1 = base + ((xb ^ m1) << 3) - (KADJ - SMS * 8u);
        q0 = *(const uint2*)(tileb + off0);
        q1 = *(const uint2*)(tileb + off1);
    };
    // Phase 2: weights + (m,d) bilinear.
    auto interp = [&](unsigned long long q, unsigned long long fm,
                      uint2 q0, uint2 q1) -> __half2 {
        unsigned long long t, w;
        ADD2(t, fm, NMAG2);
        FMA2(w, t, NEG12, q);
        float wxf, wyf; upk_f(w, wxf, wyf);
        __half2 wpk = __floats2half2_rn(wxf, wyf);
        __half2 wx2 = __low2half2(wpk);
        __half2 wy2 = __high2half2(wpk);
        __half2 m0h = *(__half2*)&q0.x, d0h = *(__half2*)&q0.y;
        __half2 m1h = *(__half2*)&q1.x, d1h = *(__half2*)&q1.y;
        __half2 r0h = __hfma2(wx2, d0h, m0h);
        __half2 r1h = __hfma2(wx2, d1h, m1h);
        return __hfma2(wy2, __hsub2(r1h, r0h), r0h);
    };

    float sc = scale[b];

    for (int ang0 = aStart; ang0 < aEnd; ang0 += CHUNK) {
        int na = aEnd - ang0; if (na > CHUNK) na = CHUNK;
        int items = na * ND;
        int tabBase = ang0 - aStart;

        for (int it = tid; it < items; it += RBLK) {
            int al = it / ND;
            int j  = it - al * ND;
            float4 T = tab0[tabBase + al];
            float s = T.x, c = T.y, is = T.z, ic = T.w;
            float u  = (float)j - 149.5f;
            float bx = fmaf(c,  u, fmaf(-149.5f, s, 73.5f));
            float by = fmaf(-s, u, fmaf(-149.5f, c, 73.5f));

            const float LO = 0.999f, HI = 146.001f;
            float rxa = (LO - bx) * is, rxb = (HI - bx) * is;
            float rya = (LO - by) * ic, ryb = (HI - by) * ic;
            float t0 = fmaxf(0.f,   fmaxf(fminf(rxa, rxb), fminf(rya, ryb)));
            float t1 = fminf(299.f, fminf(fmaxf(rxa, rxb), fmaxf(rya, ryb)));

            float S = 0.f, A = 0.f;
            if (t0 <= t1) {
                int i0 = (int)ceilf(t0);
                int i1 = (int)floorf(t1);
                int n  = i1 - i0 + 1;
                float lx0 = fmaf(s, (float)i0, bx - 0.5f);
                float ly0 = fmaf(c, (float)i0, by);
                unsigned long long st1 = pk2(s, c);
                unsigned long long st4 = pk2(4.f * s, 4.f * c);
                unsigned long long p0 = pk2(lx0, ly0);
                unsigned long long p1, p2, p3;
                ADD2(p1, p0, st1);
                ADD2(p2, p1, st1);
                ADD2(p3, p2, st1);
                int k = 0;
#pragma unroll 1
                for (; k + 3 < n; k += 4) {
                    unsigned long long fa, fb, fc, fd;
                    uint2 a0, a1, b0, b1, c0, c1, d0, d1;
                    fetch(p0, fa, a0, a1);       // 8 LDS.64 issued up front
                    fetch(p1, fb, b0, b1);
                    fetch(p2, fc, c0, c1);
                    fetch(p3, fd, d0, d1);
                    __half2 ra = interp(p0, fa, a0, a1);
                    __half2 rb = interp(p1, fb, b0, b1);
                    __half2 rc = interp(p2, fc, c0, c1);
                    __half2 rd = interp(p3, fd, d0, d1);
                    ADD2(p0, p0, st4);
                    ADD2(p1, p1, st4);
                    ADD2(p2, p2, st4);
                    ADD2(p3, p3, st4);
                    __half2 qq = __hadd2(__hadd2(ra, rb), __hadd2(rc, rd));
                    float2 f = __half22float2(qq);
                    S += f.x; A += f.y;
                }
#pragma unroll 1
                for (; k < n; ++k) {
                    unsigned long long fa; uint2 a0, a1;
                    fetch(p0, fa, a0, a1);
                    float2 f = __half22float2(interp(p0, fa, a0, a1));
                    S += f.x; A += f.y;
                    ADD2(p0, p0, st1);
                }
            }
            srow[al * ND + j] = S * __expf(-2.0f * A);
        }
        __syncthreads();

        float* o_base = out + (b * NA + ang0) * ND;
        for (int it = tid; it < items; it += RBLK) {
            int al = it / ND;
            int j  = it - al * ND;
            float4 E = tab1[tabBase + al];
            float e1 = E.x, e2 = E.y, norm = E.z;
            const float* row = srow + al * ND;
            int jm2 = j - 2; jm2 = jm2 < 0 ? -jm2 : jm2;
            int jm1 = j - 1; jm1 = jm1 < 0 ? -jm1 : jm1;
            int jp1 = j + 1; jp1 = jp1 > ND - 1 ? 2 * (ND - 1) - jp1 : jp1;
            int jp2 = j + 2; jp2 = jp2 > ND - 1 ? 2 * (ND - 1) - jp2 : jp2;
            float acc = row[j]
                      + e1 * (row[jm1] + row[jp1])
                      + e2 * (row[jm2] + row[jp2]);
            o_base[al * ND + j] = acc * norm * sc;
        }
        __syncthreads();
    }
}

// ---------------------------------------------------------------------------
extern "C" void kernel_launch(void* const* d_in, const int* in_sizes, int n_in,
                              void* d_out, int out_size) {
    const float* img   = (const float*)d_in[0];
    const float* att   = (const float*)d_in[1];
    const float* scale = (const float*)d_in[2];
    float* out = (float*)d_out;
    (void)in_sizes; (void)n_in; (void)out_size;

    int prep_smem = (128 + TS) * (CPB + 1) * (int)sizeof(float2);
    cudaFuncSetAttribute(prep_kernel,  cudaFuncAttributeMaxDynamicSharedMemorySize,
                         prep_smem);
    cudaFuncSetAttribute(radon_kernel, cudaFuncAttributeMaxDynamicSharedMemorySize,
                         RAD_SMEM);

    prep_kernel<<<dim3(NSPLIT, NB), 512, prep_smem>>>(img, att);
    radon_kernel<<<dim3(NBLK, NB), RBLK, RAD_SMEM>>>(scale, out);
}